// round 3
// baseline (speedup 1.0000x reference)
#include <cuda_runtime.h>
#include <math.h>

// Problem constants (fixed by setup_inputs)
#define B_      2
#define C_      2048
#define D_      256
#define H_      8
#define L_      4
#define FF_     2048
#define DH_     32
#define NOUT_   16384          // C_ * STRIDE
#define M_      (B_ * C_)      // 4096 rows everywhere
#define KTOK_   60

// -------------------- scratch (device globals; no allocs allowed) --------------------
__device__ float g_x [M_ * D_];
__device__ float g_h [M_ * D_];
__device__ float g_q [M_ * D_];
__device__ float g_k [M_ * D_];
__device__ float g_v [M_ * D_];
__device__ float g_ao[M_ * D_];
__device__ float g_ff[M_ * FF_];
__device__ float g_cos[C_ * 16];
__device__ float g_sin[C_ * 16];

// TF32 input quantization (round-to-nearest-away), emulating XLA/cuBLAS TF32 matmuls.
__device__ __forceinline__ float tf32r(float x) {
    float r;
    asm("cvt.rna.tf32.f32 %0, %1;" : "=f"(r) : "f"(x));
    return r;
}

// -------------------- generic tiled GEMM (TF32-quantized inputs, fp32 accumulate) ------
// C = A(MxK) @ B(KxN) + bias [+res] [relu];  BM=BN=128, BK=8, 256 threads, 8x8/thread.
template<bool RELU, bool RES>
__global__ __launch_bounds__(256) void sgemm_kernel(
    const float* __restrict__ A, const float* __restrict__ Bm,
    const float* __restrict__ bias, const float* __restrict__ res,
    float* __restrict__ Cm, int M, int N, int K)
{
    __shared__ float As[8][128];
    __shared__ float Bs[8][128];

    const int tid  = threadIdx.x;
    const int tx   = tid & 15;
    const int ty   = tid >> 4;
    const int row0 = blockIdx.y * 128;
    const int col0 = blockIdx.x * 128;

    const int aRow = tid >> 1;
    const int aCol = (tid & 1) * 4;
    const int bRow = tid >> 5;
    const int bCol = (tid & 31) * 4;

    float acc[8][8];
#pragma unroll
    for (int i = 0; i < 8; i++)
#pragma unroll
        for (int j = 0; j < 8; j++) acc[i][j] = 0.f;

    for (int k0 = 0; k0 < K; k0 += 8) {
        float4 a4 = *(const float4*)(A + (size_t)(row0 + aRow) * K + k0 + aCol);
        As[aCol + 0][aRow] = tf32r(a4.x);
        As[aCol + 1][aRow] = tf32r(a4.y);
        As[aCol + 2][aRow] = tf32r(a4.z);
        As[aCol + 3][aRow] = tf32r(a4.w);
        float4 b4 = *(const float4*)(Bm + (size_t)(k0 + bRow) * N + col0 + bCol);
        Bs[bRow][bCol + 0] = tf32r(b4.x);
        Bs[bRow][bCol + 1] = tf32r(b4.y);
        Bs[bRow][bCol + 2] = tf32r(b4.z);
        Bs[bRow][bCol + 3] = tf32r(b4.w);
        __syncthreads();
#pragma unroll
        for (int kk = 0; kk < 8; kk++) {
            float ra[8], rb[8];
#pragma unroll
            for (int i = 0; i < 8; i++) ra[i] = As[kk][ty * 8 + i];
#pragma unroll
            for (int j = 0; j < 8; j++) rb[j] = Bs[kk][tx * 8 + j];
#pragma unroll
            for (int i = 0; i < 8; i++)
#pragma unroll
                for (int j = 0; j < 8; j++)
                    acc[i][j] += ra[i] * rb[j];
        }
        __syncthreads();
    }

#pragma unroll
    for (int i = 0; i < 8; i++) {
        int r = row0 + ty * 8 + i;
#pragma unroll
        for (int j = 0; j < 8; j++) {
            int c = col0 + tx * 8 + j;
            float vv = acc[i][j] + bias[c];
            if (RES)  vv += res[(size_t)r * N + c];
            if (RELU) vv = fmaxf(vv, 0.f);
            Cm[(size_t)r * N + c] = vv;
        }
    }
}

// -------------------- fused QKV GEMM (z-slice selects W/b/out), TF32 inputs ------------
__global__ __launch_bounds__(256) void qkv_kernel(
    const float* __restrict__ A,
    const float* __restrict__ Wq, const float* __restrict__ bq, float* __restrict__ Oq,
    const float* __restrict__ Wk, const float* __restrict__ bk, float* __restrict__ Ok,
    const float* __restrict__ Wv, const float* __restrict__ bv, float* __restrict__ Ov)
{
    const float* Bm;  const float* bias;  float* Cm;
    if (blockIdx.z == 0)      { Bm = Wq; bias = bq; Cm = Oq; }
    else if (blockIdx.z == 1) { Bm = Wk; bias = bk; Cm = Ok; }
    else                      { Bm = Wv; bias = bv; Cm = Ov; }

    __shared__ float As[8][128];
    __shared__ float Bs[8][128];

    const int tid  = threadIdx.x;
    const int tx   = tid & 15;
    const int ty   = tid >> 4;
    const int row0 = blockIdx.y * 128;
    const int col0 = blockIdx.x * 128;

    const int aRow = tid >> 1;
    const int aCol = (tid & 1) * 4;
    const int bRow = tid >> 5;
    const int bCol = (tid & 31) * 4;

    float acc[8][8];
#pragma unroll
    for (int i = 0; i < 8; i++)
#pragma unroll
        for (int j = 0; j < 8; j++) acc[i][j] = 0.f;

    for (int k0 = 0; k0 < D_; k0 += 8) {
        float4 a4 = *(const float4*)(A + (size_t)(row0 + aRow) * D_ + k0 + aCol);
        As[aCol + 0][aRow] = tf32r(a4.x);
        As[aCol + 1][aRow] = tf32r(a4.y);
        As[aCol + 2][aRow] = tf32r(a4.z);
        As[aCol + 3][aRow] = tf32r(a4.w);
        float4 b4 = *(const float4*)(Bm + (size_t)(k0 + bRow) * D_ + col0 + bCol);
        Bs[bRow][bCol + 0] = tf32r(b4.x);
        Bs[bRow][bCol + 1] = tf32r(b4.y);
        Bs[bRow][bCol + 2] = tf32r(b4.z);
        Bs[bRow][bCol + 3] = tf32r(b4.w);
        __syncthreads();
#pragma unroll
        for (int kk = 0; kk < 8; kk++) {
            float ra[8], rb[8];
#pragma unroll
            for (int i = 0; i < 8; i++) ra[i] = As[kk][ty * 8 + i];
#pragma unroll
            for (int j = 0; j < 8; j++) rb[j] = Bs[kk][tx * 8 + j];
#pragma unroll
            for (int i = 0; i < 8; i++)
#pragma unroll
                for (int j = 0; j < 8; j++)
                    acc[i][j] += ra[i] * rb[j];
        }
        __syncthreads();
    }

#pragma unroll
    for (int i = 0; i < 8; i++) {
        int r = row0 + ty * 8 + i;
#pragma unroll
        for (int j = 0; j < 8; j++) {
            int c = col0 + tx * 8 + j;
            Cm[(size_t)r * D_ + c] = acc[i][j] + bias[c];
        }
    }
}

// -------------------- layernorm: one block (256 thr) per row, D=256 --------------------
__global__ __launch_bounds__(256) void ln_kernel(
    const float* __restrict__ x, const float* __restrict__ g,
    const float* __restrict__ b, float* __restrict__ out)
{
    const int row = blockIdx.x;
    const int d   = threadIdx.x;
    float v = x[(size_t)row * D_ + d];

    float s = v, s2 = v * v;
#pragma unroll
    for (int o = 16; o > 0; o >>= 1) {
        s  += __shfl_xor_sync(0xffffffffu, s,  o);
        s2 += __shfl_xor_sync(0xffffffffu, s2, o);
    }
    __shared__ float ws[8], ws2[8];
    const int w = d >> 5, lane = d & 31;
    if (lane == 0) { ws[w] = s; ws2[w] = s2; }
    __syncthreads();
    if (w == 0) {
        float a  = (lane < 8) ? ws[lane]  : 0.f;
        float a2 = (lane < 8) ? ws2[lane] : 0.f;
#pragma unroll
        for (int o = 4; o > 0; o >>= 1) {
            a  += __shfl_xor_sync(0xffffffffu, a,  o);
            a2 += __shfl_xor_sync(0xffffffffu, a2, o);
        }
        if (lane == 0) { ws[0] = a; ws2[0] = a2; }
    }
    __syncthreads();
    const float mean = ws[0]  * (1.f / 256.f);
    const float var  = ws2[0] * (1.f / 256.f) - mean * mean;
    out[(size_t)row * D_ + d] = (v - mean) * rsqrtf(var + 1e-5f) * g[d] + b[d];
}

// -------------------- RoPE tables (double-precision trig of fp32-rounded angle) --------
__global__ void rope_tables_kernel()
{
    const int t = blockIdx.x * blockDim.x + threadIdx.x;   // C_*16 threads
    const int i = t & 15;
    const int c = t >> 4;
    const float invf = (float)(1.0 / pow(10000.0, (double)i / 16.0));
    const float angf = (float)c * invf;                    // fp32 rounding like reference
    g_cos[t] = (float)cos((double)angf);
    g_sin[t] = (float)sin((double)angf);
}

// -------------------- RoPE in-place on q AND k ----------------------------------------
__global__ void rope_kernel(float* __restrict__ q, float* __restrict__ k)
{
    const int tid = blockIdx.x * blockDim.x + threadIdx.x;  // M_*H_*16 threads
    const int i = tid & 15;
    const int h = (tid >> 4) & 7;
    const int r = tid >> 7;
    const int c = r & (C_ - 1);
    const float cs = g_cos[c * 16 + i];
    const float sn = g_sin[c * 16 + i];
    const size_t off = (size_t)r * D_ + h * DH_;
    {
        float* p = q + off;
        const float t1 = p[i], t2 = p[i + 16];
        p[i]      = t1 * cs - t2 * sn;
        p[i + 16] = t1 * sn + t2 * cs;
    }
    {
        float* p = k + off;
        const float t1 = p[i], t2 = p[i + 16];
        p[i]      = t1 * cs - t2 * sn;
        p[i + 16] = t1 * sn + t2 * cs;
    }
}

// -------------------- windowed circular attention, TF32 einsum emulation --------------
// One warp per (b,h,q). Exact two-phase softmax; scores cached in SMEM.
__global__ __launch_bounds__(128) void attn_kernel(
    const float* __restrict__ q, const float* __restrict__ k,
    const float* __restrict__ v, float* __restrict__ out)
{
    __shared__ float sbuf[4][64];
    const int warp = (blockIdx.x * blockDim.x + threadIdx.x) >> 5;  // (b,h,c)
    const int wib  = (threadIdx.x >> 5);
    const int lane = threadIdx.x & 31;                              // dim index
    const int c = warp & (C_ - 1);
    const int h = (warp >> 11) & (H_ - 1);
    const int b = warp >> 14;
    const int qrow = b * C_ + c;
    const float scale = 0.17677669529663687f;                       // 1/sqrt(32)

    const float qt = tf32r(q[(size_t)qrow * D_ + h * DH_ + lane]);

    // Phase 1: scores (tf32 inputs, fp32 accumulate, scale after) + max
    float m = -INFINITY;
    for (int j = 0; j < KTOK_; j++) {
        int kc = c - j; if (kc < 0) kc += C_;
        const size_t base = (size_t)(b * C_ + kc) * D_ + h * DH_ + lane;
        float s = qt * tf32r(k[base]);
#pragma unroll
        for (int o = 16; o > 0; o >>= 1) s += __shfl_xor_sync(0xffffffffu, s, o);
        s *= scale;
        if (lane == 0) sbuf[wib][j] = s;
        m = fmaxf(m, s);
    }
    __syncwarp();

    // Phase 2: denom
    float denom = 0.f;
    for (int j = 0; j < KTOK_; j++) denom += __expf(sbuf[wib][j] - m);
    const float invd = 1.f / denom;

    // Phase 3: o = sum_j tf32(w_j) * tf32(v_j)
    float acc = 0.f;
    for (int j = 0; j < KTOK_; j++) {
        int kc = c - j; if (kc < 0) kc += C_;
        const size_t base = (size_t)(b * C_ + kc) * D_ + h * DH_ + lane;
        const float w = tf32r(__expf(sbuf[wib][j] - m) * invd);
        acc += w * tf32r(v[base]);
    }
    out[(size_t)qrow * D_ + h * DH_ + lane] = acc;
}

// -------------------- host orchestration --------------------
extern "C" void kernel_launch(void* const* d_in, const int* in_sizes, int n_in,
                              void* d_out, int out_size)
{
    const float* tok   = (const float*)d_in[0];
    const float* W_in  = (const float*)d_in[1];
    const float* b_in  = (const float*)d_in[2];
    const float* Wq    = (const float*)d_in[3];
    const float* bq    = (const float*)d_in[4];
    const float* Wk    = (const float*)d_in[5];
    const float* bk    = (const float*)d_in[6];
    const float* Wv    = (const float*)d_in[7];
    const float* bv    = (const float*)d_in[8];
    const float* Wo    = (const float*)d_in[9];
    const float* bo    = (const float*)d_in[10];
    const float* ln1g  = (const float*)d_in[11];
    const float* ln1b  = (const float*)d_in[12];
    const float* ln2g  = (const float*)d_in[13];
    const float* ln2b  = (const float*)d_in[14];
    const float* W1    = (const float*)d_in[15];
    const float* b1    = (const float*)d_in[16];
    const float* W2    = (const float*)d_in[17];
    const float* b2    = (const float*)d_in[18];
    const float* W_out = (const float*)d_in[19];
    const float* b_out = (const float*)d_in[20];
    float* out = (float*)d_out;

    float *x, *h, *q, *k, *v, *ao, *ff;
    cudaGetSymbolAddress((void**)&x,  g_x);
    cudaGetSymbolAddress((void**)&h,  g_h);
    cudaGetSymbolAddress((void**)&q,  g_q);
    cudaGetSymbolAddress((void**)&k,  g_k);
    cudaGetSymbolAddress((void**)&v,  g_v);
    cudaGetSymbolAddress((void**)&ao, g_ao);
    cudaGetSymbolAddress((void**)&ff, g_ff);

    const dim3 gD  (D_   / 128, M_ / 128);      // (2, 32)
    const dim3 gQKV(D_   / 128, M_ / 128, 3);   // (2, 32, 3)
    const dim3 gFF (FF_  / 128, M_ / 128);      // (16, 32)
    const dim3 gO  (NOUT_/ 128, M_ / 128);      // (128, 32)

    rope_tables_kernel<<<(C_ * 16) / 256, 256>>>();

    // x = tok @ W_in + b_in   (K = 8)
    sgemm_kernel<false, false><<<gD, 256>>>(tok, W_in, b_in, nullptr, x, M_, D_, 8);

    for (int l = 0; l < L_; l++) {
        ln_kernel<<<M_, 256>>>(x, ln1g + l * D_, ln1b + l * D_, h);

        qkv_kernel<<<gQKV, 256>>>(h,
            Wq + (size_t)l * D_ * D_, bq + l * D_, q,
            Wk + (size_t)l * D_ * D_, bk + l * D_, k,
            Wv + (size_t)l * D_ * D_, bv + l * D_, v);

        rope_kernel<<<(M_ * H_ * 16) / 256, 256>>>(q, k);

        attn_kernel<<<(B_ * H_ * C_ * 32) / 128, 128>>>(q, k, v, ao);

        // x = x + ao @ Wo + bo
        sgemm_kernel<false, true><<<gD, 256>>>(ao, Wo + (size_t)l * D_ * D_, bo + l * D_, x, x, M_, D_, D_);

        ln_kernel<<<M_, 256>>>(x, ln2g + l * D_, ln2b + l * D_, h);

        // ff = relu(h @ W1 + b1)
        sgemm_kernel<true, false><<<gFF, 256>>>(h, W1 + (size_t)l * D_ * FF_, b1 + l * FF_, nullptr, ff, M_, FF_, D_);
        // x = x + ff @ W2 + b2
        sgemm_kernel<false, true><<<gD, 256>>>(ff, W2 + (size_t)l * FF_ * D_, b2 + l * D_, x, x, M_, D_, FF_);
    }

    // out = x @ W_out + b_out
    sgemm_kernel<false, false><<<gO, 256>>>(x, W_out, b_out, nullptr, out, M_, NOUT_, D_);
}

// round 4
// speedup vs baseline: 2.5591x; 2.5591x over previous
#include <cuda_runtime.h>
#include <math.h>
#include <stdint.h>

// Problem constants (fixed by setup_inputs)
#define B_      2
#define C_      2048
#define D_      256
#define H_      8
#define L_      4
#define FF_     2048
#define DH_     32
#define NOUT_   16384          // C_ * STRIDE
#define M_      (B_ * C_)      // 4096 rows everywhere
#define KTOK_   60

// -------------------- scratch (device globals; no allocs allowed) --------------------
__device__ float g_x [M_ * D_];
__device__ float g_h [M_ * D_];
__device__ float g_q [M_ * D_];
__device__ float g_k [M_ * D_];
__device__ float g_v [M_ * D_];
__device__ float g_ao[M_ * D_];
__device__ float g_ff[M_ * FF_];
__device__ float g_cos[C_ * 16];
__device__ float g_sin[C_ * 16];

// TF32 input quantization (round-to-nearest-away), matching XLA/cuBLAS TF32 matmuls.
__device__ __forceinline__ float tf32r(float x) {
    float r;
    asm("cvt.rna.tf32.f32 %0, %1;" : "=f"(r) : "f"(x));
    return r;
}
__device__ __forceinline__ uint32_t fbits(float x) { return __float_as_uint(x); }

// ==================== TF32 tensor-core GEMM ====================
// C = A(MxK) @ B(KxN) + bias [+res] [relu]
// BM=128, BN=128, BK=32, 256 threads (8 warps in 2x4), warp tile 64x32,
// mma.sync.aligned.m16n8k8.tf32, fp32 accumulate.
template<bool RELU, bool RES, bool QKV3>
__global__ __launch_bounds__(256) void tgemm_kernel(
    const float* __restrict__ A,
    const float* __restrict__ B0, const float* __restrict__ bias0, float* __restrict__ C0,
    const float* __restrict__ res,
    int N, int K,
    const float* B1, const float* bias1, float* C1,
    const float* B2, const float* bias2, float* C2)
{
    const float* Bm = B0;  const float* bias = bias0;  float* Cm = C0;
    if (QKV3) {
        if (blockIdx.z == 1)      { Bm = B1; bias = bias1; Cm = C1; }
        else if (blockIdx.z == 2) { Bm = B2; bias = bias2; Cm = C2; }
    }

    __shared__ float As[128][36];   // stride 36: conflict-free A-frag loads
    __shared__ float Bs[32][136];   // stride 136: conflict-free B-frag loads

    const int tid  = threadIdx.x;
    const int warp = tid >> 5;
    const int lane = tid & 31;
    const int wm   = warp >> 2;           // 0..1 -> 64 rows
    const int wn   = warp & 3;            // 0..3 -> 32 cols
    const int gid  = lane >> 2;           // 0..7
    const int tid4 = lane & 3;            // 0..3

    const int row0 = blockIdx.y * 128;
    const int col0 = blockIdx.x * 128;

    // gmem load mapping
    const int lr  = tid >> 3;             // 0..31
    const int lc4 = (tid & 7) * 4;        // 0,4,..,28

    float acc[4][4][4];
#pragma unroll
    for (int i = 0; i < 4; i++)
#pragma unroll
        for (int j = 0; j < 4; j++)
#pragma unroll
            for (int t = 0; t < 4; t++) acc[i][j][t] = 0.f;

    for (int k0 = 0; k0 < K; k0 += 32) {
        // A tile: 128x32.  thread -> rows lr+{0,32,64,96}, cols lc4..lc4+3
#pragma unroll
        for (int s = 0; s < 4; s++) {
            const int r = lr + s * 32;
            float4 a4 = *(const float4*)(A + (size_t)(row0 + r) * K + k0 + lc4);
            As[r][lc4 + 0] = tf32r(a4.x);
            As[r][lc4 + 1] = tf32r(a4.y);
            As[r][lc4 + 2] = tf32r(a4.z);
            As[r][lc4 + 3] = tf32r(a4.w);
        }
        // B tile: 32x128.  thread -> row lr, cols lc4+{0,32,64,96}
#pragma unroll
        for (int s = 0; s < 4; s++) {
            const int c = lc4 + s * 32;
            float4 b4 = *(const float4*)(Bm + (size_t)(k0 + lr) * N + col0 + c);
            Bs[lr][c + 0] = tf32r(b4.x);
            Bs[lr][c + 1] = tf32r(b4.y);
            Bs[lr][c + 2] = tf32r(b4.z);
            Bs[lr][c + 3] = tf32r(b4.w);
        }
        __syncthreads();

#pragma unroll
        for (int kk = 0; kk < 32; kk += 8) {
            uint32_t af[4][4];
#pragma unroll
            for (int mf = 0; mf < 4; mf++) {
                const int ar = wm * 64 + mf * 16 + gid;
                af[mf][0] = fbits(As[ar    ][kk + tid4    ]);
                af[mf][1] = fbits(As[ar + 8][kk + tid4    ]);
                af[mf][2] = fbits(As[ar    ][kk + tid4 + 4]);
                af[mf][3] = fbits(As[ar + 8][kk + tid4 + 4]);
            }
            uint32_t bf[4][2];
#pragma unroll
            for (int nf = 0; nf < 4; nf++) {
                const int bc = wn * 32 + nf * 8 + gid;
                bf[nf][0] = fbits(Bs[kk + tid4    ][bc]);
                bf[nf][1] = fbits(Bs[kk + tid4 + 4][bc]);
            }
#pragma unroll
            for (int mf = 0; mf < 4; mf++)
#pragma unroll
                for (int nf = 0; nf < 4; nf++) {
                    asm volatile(
                        "mma.sync.aligned.m16n8k8.row.col.f32.tf32.tf32.f32 "
                        "{%0,%1,%2,%3}, {%4,%5,%6,%7}, {%8,%9}, {%0,%1,%2,%3};"
                        : "+f"(acc[mf][nf][0]), "+f"(acc[mf][nf][1]),
                          "+f"(acc[mf][nf][2]), "+f"(acc[mf][nf][3])
                        : "r"(af[mf][0]), "r"(af[mf][1]), "r"(af[mf][2]), "r"(af[mf][3]),
                          "r"(bf[nf][0]), "r"(bf[nf][1]));
                }
        }
        __syncthreads();
    }

    // Epilogue
#pragma unroll
    for (int mf = 0; mf < 4; mf++) {
        const int r = row0 + wm * 64 + mf * 16 + gid;
#pragma unroll
        for (int nf = 0; nf < 4; nf++) {
            const int c = col0 + wn * 32 + nf * 8 + tid4 * 2;
            // (c0,c1) at row r ; (c2,c3) at row r+8
            float v0 = acc[mf][nf][0] + bias[c];
            float v1 = acc[mf][nf][1] + bias[c + 1];
            float v2 = acc[mf][nf][2] + bias[c];
            float v3 = acc[mf][nf][3] + bias[c + 1];
            if (RES) {
                const float2 r0 = *(const float2*)(res + (size_t)r * N + c);
                const float2 r1 = *(const float2*)(res + (size_t)(r + 8) * N + c);
                v0 += r0.x; v1 += r0.y; v2 += r1.x; v3 += r1.y;
            }
            if (RELU) {
                v0 = fmaxf(v0, 0.f); v1 = fmaxf(v1, 0.f);
                v2 = fmaxf(v2, 0.f); v3 = fmaxf(v3, 0.f);
            }
            *(float2*)(Cm + (size_t)r * N + c)       = make_float2(v0, v1);
            *(float2*)(Cm + (size_t)(r + 8) * N + c) = make_float2(v2, v3);
        }
    }
}

// -------------------- FFMA GEMM for the K=8 embed only --------------------
__global__ __launch_bounds__(256) void embed_kernel(
    const float* __restrict__ A, const float* __restrict__ Bm,
    const float* __restrict__ bias, float* __restrict__ Cm, int M, int N, int K)
{
    __shared__ float As[8][128];
    __shared__ float Bs[8][128];
    const int tid  = threadIdx.x;
    const int tx   = tid & 15;
    const int ty   = tid >> 4;
    const int row0 = blockIdx.y * 128;
    const int col0 = blockIdx.x * 128;
    const int aRow = tid >> 1;
    const int aCol = (tid & 1) * 4;
    const int bRow = tid >> 5;
    const int bCol = (tid & 31) * 4;

    float acc[8][8];
#pragma unroll
    for (int i = 0; i < 8; i++)
#pragma unroll
        for (int j = 0; j < 8; j++) acc[i][j] = 0.f;

    for (int k0 = 0; k0 < K; k0 += 8) {
        float4 a4 = *(const float4*)(A + (size_t)(row0 + aRow) * K + k0 + aCol);
        As[aCol + 0][aRow] = tf32r(a4.x);
        As[aCol + 1][aRow] = tf32r(a4.y);
        As[aCol + 2][aRow] = tf32r(a4.z);
        As[aCol + 3][aRow] = tf32r(a4.w);
        float4 b4 = *(const float4*)(Bm + (size_t)(k0 + bRow) * N + col0 + bCol);
        Bs[bRow][bCol + 0] = tf32r(b4.x);
        Bs[bRow][bCol + 1] = tf32r(b4.y);
        Bs[bRow][bCol + 2] = tf32r(b4.z);
        Bs[bRow][bCol + 3] = tf32r(b4.w);
        __syncthreads();
#pragma unroll
        for (int kk = 0; kk < 8; kk++) {
            float ra[8], rb[8];
#pragma unroll
            for (int i = 0; i < 8; i++) ra[i] = As[kk][ty * 8 + i];
#pragma unroll
            for (int j = 0; j < 8; j++) rb[j] = Bs[kk][tx * 8 + j];
#pragma unroll
            for (int i = 0; i < 8; i++)
#pragma unroll
                for (int j = 0; j < 8; j++)
                    acc[i][j] += ra[i] * rb[j];
        }
        __syncthreads();
    }
#pragma unroll
    for (int i = 0; i < 8; i++) {
        int r = row0 + ty * 8 + i;
#pragma unroll
        for (int j = 0; j < 8; j++) {
            int c = col0 + tx * 8 + j;
            Cm[(size_t)r * N + c] = acc[i][j] + bias[c];
        }
    }
}

// -------------------- layernorm: one block (256 thr) per row, D=256 --------------------
__global__ __launch_bounds__(256) void ln_kernel(
    const float* __restrict__ x, const float* __restrict__ g,
    const float* __restrict__ b, float* __restrict__ out)
{
    const int row = blockIdx.x;
    const int d   = threadIdx.x;
    float v = x[(size_t)row * D_ + d];

    float s = v, s2 = v * v;
#pragma unroll
    for (int o = 16; o > 0; o >>= 1) {
        s  += __shfl_xor_sync(0xffffffffu, s,  o);
        s2 += __shfl_xor_sync(0xffffffffu, s2, o);
    }
    __shared__ float ws[8], ws2[8];
    const int w = d >> 5, lane = d & 31;
    if (lane == 0) { ws[w] = s; ws2[w] = s2; }
    __syncthreads();
    if (w == 0) {
        float a  = (lane < 8) ? ws[lane]  : 0.f;
        float a2 = (lane < 8) ? ws2[lane] : 0.f;
#pragma unroll
        for (int o = 4; o > 0; o >>= 1) {
            a  += __shfl_xor_sync(0xffffffffu, a,  o);
            a2 += __shfl_xor_sync(0xffffffffu, a2, o);
        }
        if (lane == 0) { ws[0] = a; ws2[0] = a2; }
    }
    __syncthreads();
    const float mean = ws[0]  * (1.f / 256.f);
    const float var  = ws2[0] * (1.f / 256.f) - mean * mean;
    out[(size_t)row * D_ + d] = (v - mean) * rsqrtf(var + 1e-5f) * g[d] + b[d];
}

// -------------------- RoPE tables (double-precision trig of fp32-rounded angle) --------
__global__ void rope_tables_kernel()
{
    const int t = blockIdx.x * blockDim.x + threadIdx.x;   // C_*16 threads
    const int i = t & 15;
    const int c = t >> 4;
    const float invf = (float)(1.0 / pow(10000.0, (double)i / 16.0));
    const float angf = (float)c * invf;                    // fp32 rounding like reference
    g_cos[t] = (float)cos((double)angf);
    g_sin[t] = (float)sin((double)angf);
}

// -------------------- RoPE in-place on q AND k ----------------------------------------
__global__ void rope_kernel(float* __restrict__ q, float* __restrict__ k)
{
    const int tid = blockIdx.x * blockDim.x + threadIdx.x;  // M_*H_*16 threads
    const int i = tid & 15;
    const int h = (tid >> 4) & 7;
    const int r = tid >> 7;
    const int c = r & (C_ - 1);
    const float cs = g_cos[c * 16 + i];
    const float sn = g_sin[c * 16 + i];
    const size_t off = (size_t)r * D_ + h * DH_;
    {
        float* p = q + off;
        const float t1 = p[i], t2 = p[i + 16];
        p[i]      = t1 * cs - t2 * sn;
        p[i + 16] = t1 * sn + t2 * cs;
    }
    {
        float* p = k + off;
        const float t1 = p[i], t2 = p[i + 16];
        p[i]      = t1 * cs - t2 * sn;
        p[i + 16] = t1 * sn + t2 * cs;
    }
}

// -------------------- windowed circular attention, TF32 einsum emulation --------------
// One warp per (b,h,q). Exact two-phase softmax; scores cached in SMEM.
__global__ __launch_bounds__(128) void attn_kernel(
    const float* __restrict__ q, const float* __restrict__ k,
    const float* __restrict__ v, float* __restrict__ out)
{
    __shared__ float sbuf[4][64];
    const int warp = (blockIdx.x * blockDim.x + threadIdx.x) >> 5;  // (b,h,c)
    const int wib  = (threadIdx.x >> 5);
    const int lane = threadIdx.x & 31;                              // dim index
    const int c = warp & (C_ - 1);
    const int h = (warp >> 11) & (H_ - 1);
    const int b = warp >> 14;
    const int qrow = b * C_ + c;
    const float scale = 0.17677669529663687f;                       // 1/sqrt(32)

    const float qt = tf32r(q[(size_t)qrow * D_ + h * DH_ + lane]);

    // Phase 1: scores (tf32 inputs, fp32 accumulate, scale after) + max
    float m = -INFINITY;
    for (int j = 0; j < KTOK_; j++) {
        int kc = c - j; if (kc < 0) kc += C_;
        const size_t base = (size_t)(b * C_ + kc) * D_ + h * DH_ + lane;
        float s = qt * tf32r(k[base]);
#pragma unroll
        for (int o = 16; o > 0; o >>= 1) s += __shfl_xor_sync(0xffffffffu, s, o);
        s *= scale;
        if (lane == 0) sbuf[wib][j] = s;
        m = fmaxf(m, s);
    }
    __syncwarp();

    // Phase 2: denom
    float denom = 0.f;
    for (int j = 0; j < KTOK_; j++) denom += __expf(sbuf[wib][j] - m);
    const float invd = 1.f / denom;

    // Phase 3: o = sum_j tf32(w_j) * tf32(v_j)
    float acc = 0.f;
    for (int j = 0; j < KTOK_; j++) {
        int kc = c - j; if (kc < 0) kc += C_;
        const size_t base = (size_t)(b * C_ + kc) * D_ + h * DH_ + lane;
        const float w = tf32r(__expf(sbuf[wib][j] - m) * invd);
        acc += w * tf32r(v[base]);
    }
    out[(size_t)qrow * D_ + h * DH_ + lane] = acc;
}

// -------------------- host orchestration --------------------
extern "C" void kernel_launch(void* const* d_in, const int* in_sizes, int n_in,
                              void* d_out, int out_size)
{
    const float* tok   = (const float*)d_in[0];
    const float* W_in  = (const float*)d_in[1];
    const float* b_in  = (const float*)d_in[2];
    const float* Wq    = (const float*)d_in[3];
    const float* bq    = (const float*)d_in[4];
    const float* Wk    = (const float*)d_in[5];
    const float* bk    = (const float*)d_in[6];
    const float* Wv    = (const float*)d_in[7];
    const float* bv    = (const float*)d_in[8];
    const float* Wo    = (const float*)d_in[9];
    const float* bo    = (const float*)d_in[10];
    const float* ln1g  = (const float*)d_in[11];
    const float* ln1b  = (const float*)d_in[12];
    const float* ln2g  = (const float*)d_in[13];
    const float* ln2b  = (const float*)d_in[14];
    const float* W1    = (const float*)d_in[15];
    const float* b1    = (const float*)d_in[16];
    const float* W2    = (const float*)d_in[17];
    const float* b2    = (const float*)d_in[18];
    const float* W_out = (const float*)d_in[19];
    const float* b_out = (const float*)d_in[20];
    float* out = (float*)d_out;

    float *x, *h, *q, *k, *v, *ao, *ff;
    cudaGetSymbolAddress((void**)&x,  g_x);
    cudaGetSymbolAddress((void**)&h,  g_h);
    cudaGetSymbolAddress((void**)&q,  g_q);
    cudaGetSymbolAddress((void**)&k,  g_k);
    cudaGetSymbolAddress((void**)&v,  g_v);
    cudaGetSymbolAddress((void**)&ao, g_ao);
    cudaGetSymbolAddress((void**)&ff, g_ff);

    const dim3 gD  (D_   / 128, M_ / 128);      // (2, 32)
    const dim3 gQKV(D_   / 128, M_ / 128, 3);   // (2, 32, 3)
    const dim3 gFF (FF_  / 128, M_ / 128);      // (16, 32)
    const dim3 gO  (NOUT_/ 128, M_ / 128);      // (128, 32)

    rope_tables_kernel<<<(C_ * 16) / 256, 256>>>();

    // x = tok @ W_in + b_in   (K = 8, FFMA path)
    embed_kernel<<<gD, 256>>>(tok, W_in, b_in, x, M_, D_, 8);

    for (int l = 0; l < L_; l++) {
        ln_kernel<<<M_, 256>>>(x, ln1g + l * D_, ln1b + l * D_, h);

        tgemm_kernel<false, false, true><<<gQKV, 256>>>(h,
            Wq + (size_t)l * D_ * D_, bq + l * D_, q, nullptr, D_, D_,
            Wk + (size_t)l * D_ * D_, bk + l * D_, k,
            Wv + (size_t)l * D_ * D_, bv + l * D_, v);

        rope_kernel<<<(M_ * H_ * 16) / 256, 256>>>(q, k);

        attn_kernel<<<(B_ * H_ * C_ * 32) / 128, 128>>>(q, k, v, ao);

        // x = x + ao @ Wo + bo
        tgemm_kernel<false, true, false><<<gD, 256>>>(ao,
            Wo + (size_t)l * D_ * D_, bo + l * D_, x, x, D_, D_,
            nullptr, nullptr, nullptr, nullptr, nullptr, nullptr);

        ln_kernel<<<M_, 256>>>(x, ln2g + l * D_, ln2b + l * D_, h);

        // ff = relu(h @ W1 + b1)
        tgemm_kernel<true, false, false><<<gFF, 256>>>(h,
            W1 + (size_t)l * D_ * FF_, b1 + l * FF_, ff, nullptr, FF_, D_,
            nullptr, nullptr, nullptr, nullptr, nullptr, nullptr);
        // x = x + ff @ W2 + b2
        tgemm_kernel<false, true, false><<<gD, 256>>>(ff,
            W2 + (size_t)l * FF_ * D_, b2 + l * D_, x, x, D_, FF_,
            nullptr, nullptr, nullptr, nullptr, nullptr, nullptr);
    }

    // out = x @ W_out + b_out
    tgemm_kernel<false, false, false><<<gO, 256>>>(x,
        W_out, b_out, out, nullptr, NOUT_, D_,
        nullptr, nullptr, nullptr, nullptr, nullptr, nullptr);
}

// round 6
// speedup vs baseline: 4.1363x; 1.6163x over previous
#include <cuda_runtime.h>
#include <math.h>
#include <stdint.h>

// Problem constants (fixed by setup_inputs)
#define B_      2
#define C_      2048
#define D_      256
#define H_      8
#define L_      4
#define FF_     2048
#define DH_     32
#define NOUT_   16384
#define M_      (B_ * C_)      // 4096
#define KTOK_   60

// -------------------- scratch --------------------
__device__ float g_x [M_ * D_];
__device__ float g_h [M_ * D_];
__device__ float g_q [M_ * D_];
__device__ float g_k [M_ * D_];
__device__ float g_v [M_ * D_];
__device__ float g_ao[M_ * D_];
__device__ float g_ff[M_ * FF_];
__device__ float g_cos[C_ * 16];
__device__ float g_sin[C_ * 16];

// TF32 input quantization (round-to-nearest-away), matching cuBLAS/XLA TF32 matmuls.
__device__ __forceinline__ float tf32r(float x) {
    float r;
    asm("cvt.rna.tf32.f32 %0, %1;" : "=f"(r) : "f"(x));
    return r;
}
__device__ __forceinline__ uint32_t qbits(float x) { return __float_as_uint(tf32r(x)); }

__device__ __forceinline__ void cp16(uint32_t saddr, const float* gptr) {
    asm volatile("cp.async.cg.shared.global [%0], [%1], 16;" :: "r"(saddr), "l"(gptr));
}
__device__ __forceinline__ void cp_commit() {
    asm volatile("cp.async.commit_group;" ::: "memory");
}
template<int N>
__device__ __forceinline__ void cp_wait() {
    asm volatile("cp.async.wait_group %0;" :: "n"(N) : "memory");
}

// ==================== TF32 tensor-core GEMM, double-buffered cp.async ====================
// C = A(MxK) @ B(KxN) + bias [+res] [relu].  BK=32.
// Warp tile: (BM/WM_)x(BN/WN_) warps, each 16*FM x 8*FN via m16n8k8.tf32.
template<int BM, int BN, int WM_, int WN_, bool RELU, bool RES, bool QKV3>
__global__ void tgemm_kernel(
    const float* __restrict__ A,
    const float* __restrict__ B0, const float* __restrict__ bias0, float* __restrict__ C0,
    const float* __restrict__ res,
    int N, int K,
    const float* B1, const float* bias1, float* C1,
    const float* B2, const float* bias2, float* C2)
{
    constexpr int THREADS = WM_ * WN_ * 32;
    constexpr int AST = 36;         // A smem stride (BK+4)
    constexpr int BST = BN + 8;     // B smem stride
    constexpr int FM  = (BM / WM_) / 16;
    constexpr int FN  = (BN / WN_) / 8;

    extern __shared__ float smem[];
    float* As = smem;                     // [2][BM][AST]
    float* Bs = smem + 2 * BM * AST;      // [2][32][BST]

    const float* Bm = B0;  const float* bias = bias0;  float* Cm = C0;
    if (QKV3) {
        if (blockIdx.z == 1)      { Bm = B1; bias = bias1; Cm = C1; }
        else if (blockIdx.z == 2) { Bm = B2; bias = bias2; Cm = C2; }
    }

    const int tid  = threadIdx.x;
    const int warp = tid >> 5;
    const int lane = tid & 31;
    const int wm   = warp / WN_;
    const int wn   = warp % WN_;
    const int gid  = lane >> 2;
    const int tid4 = lane & 3;

    const int row0 = blockIdx.y * BM;
    const int col0 = blockIdx.x * BN;

    float acc[FM][FN][4];
#pragma unroll
    for (int i = 0; i < FM; i++)
#pragma unroll
        for (int j = 0; j < FN; j++)
#pragma unroll
            for (int t = 0; t < 4; t++) acc[i][j][t] = 0.f;

    const int nk = K >> 5;

    // stage-issue lambda (A: BM x 32, B: 32 x BN)
    auto issue = [&](int t, int buf) {
        const int k0 = t << 5;
        float* Ad = As + buf * BM * AST;
        float* Bd = Bs + buf * 32 * BST;
#pragma unroll
        for (int i = 0; i < (BM * 8) / THREADS; i++) {
            const int idx = tid + i * THREADS;
            const int r   = idx >> 3;
            const int k4  = (idx & 7) * 4;
            cp16((uint32_t)__cvta_generic_to_shared(Ad + r * AST + k4),
                 A + (size_t)(row0 + r) * K + k0 + k4);
        }
#pragma unroll
        for (int i = 0; i < (BN * 8) / THREADS; i++) {
            const int idx = tid + i * THREADS;
            const int kr  = idx / (BN / 4);
            const int c4  = (idx % (BN / 4)) * 4;
            cp16((uint32_t)__cvta_generic_to_shared(Bd + kr * BST + c4),
                 Bm + (size_t)(k0 + kr) * N + col0 + c4);
        }
        cp_commit();
    };

    issue(0, 0);
    for (int t = 0; t < nk; t++) {
        if (t + 1 < nk) { issue(t + 1, (t + 1) & 1); cp_wait<1>(); }
        else            { cp_wait<0>(); }
        __syncthreads();

        const float* Ab = As + (t & 1) * BM * AST;
        const float* Bb = Bs + (t & 1) * 32 * BST;
#pragma unroll
        for (int kk = 0; kk < 32; kk += 8) {
            uint32_t af[FM][4];
#pragma unroll
            for (int mf = 0; mf < FM; mf++) {
                const int ar = wm * (BM / WM_) + mf * 16 + gid;
                af[mf][0] = qbits(Ab[(ar    ) * AST + kk + tid4    ]);
                af[mf][1] = qbits(Ab[(ar + 8) * AST + kk + tid4    ]);
                af[mf][2] = qbits(Ab[(ar    ) * AST + kk + tid4 + 4]);
                af[mf][3] = qbits(Ab[(ar + 8) * AST + kk + tid4 + 4]);
            }
            uint32_t bf[FN][2];
#pragma unroll
            for (int nf = 0; nf < FN; nf++) {
                const int bc = wn * (BN / WN_) + nf * 8 + gid;
                bf[nf][0] = qbits(Bb[(kk + tid4    ) * BST + bc]);
                bf[nf][1] = qbits(Bb[(kk + tid4 + 4) * BST + bc]);
            }
#pragma unroll
            for (int mf = 0; mf < FM; mf++)
#pragma unroll
                for (int nf = 0; nf < FN; nf++) {
                    asm volatile(
                        "mma.sync.aligned.m16n8k8.row.col.f32.tf32.tf32.f32 "
                        "{%0,%1,%2,%3}, {%4,%5,%6,%7}, {%8,%9}, {%0,%1,%2,%3};"
                        : "+f"(acc[mf][nf][0]), "+f"(acc[mf][nf][1]),
                          "+f"(acc[mf][nf][2]), "+f"(acc[mf][nf][3])
                        : "r"(af[mf][0]), "r"(af[mf][1]), "r"(af[mf][2]), "r"(af[mf][3]),
                          "r"(bf[nf][0]), "r"(bf[nf][1]));
                }
        }
        __syncthreads();
    }

    // Epilogue
#pragma unroll
    for (int mf = 0; mf < FM; mf++) {
        const int r = row0 + wm * (BM / WM_) + mf * 16 + gid;
#pragma unroll
        for (int nf = 0; nf < FN; nf++) {
            const int c = col0 + wn * (BN / WN_) + nf * 8 + tid4 * 2;
            float v0 = acc[mf][nf][0] + bias[c];
            float v1 = acc[mf][nf][1] + bias[c + 1];
            float v2 = acc[mf][nf][2] + bias[c];
            float v3 = acc[mf][nf][3] + bias[c + 1];
            if (RES) {
                const float2 r0 = *(const float2*)(res + (size_t)r * N + c);
                const float2 r1 = *(const float2*)(res + (size_t)(r + 8) * N + c);
                v0 += r0.x; v1 += r0.y; v2 += r1.x; v3 += r1.y;
            }
            if (RELU) {
                v0 = fmaxf(v0, 0.f); v1 = fmaxf(v1, 0.f);
                v2 = fmaxf(v2, 0.f); v3 = fmaxf(v3, 0.f);
            }
            *(float2*)(Cm + (size_t)r * N + c)       = make_float2(v0, v1);
            *(float2*)(Cm + (size_t)(r + 8) * N + c) = make_float2(v2, v3);
        }
    }
}

// -------------------- FFMA GEMM for the K=8 embed only --------------------
__global__ __launch_bounds__(256) void embed_kernel(
    const float* __restrict__ A, const float* __restrict__ Bm,
    const float* __restrict__ bias, float* __restrict__ Cm, int M, int N, int K)
{
    __shared__ float As[8][128];
    __shared__ float Bs[8][128];
    const int tid  = threadIdx.x;
    const int tx   = tid & 15;
    const int ty   = tid >> 4;
    const int row0 = blockIdx.y * 128;
    const int col0 = blockIdx.x * 128;
    const int aRow = tid >> 1;
    const int aCol = (tid & 1) * 4;
    const int bRow = tid >> 5;
    const int bCol = (tid & 31) * 4;

    float acc[8][8];
#pragma unroll
    for (int i = 0; i < 8; i++)
#pragma unroll
        for (int j = 0; j < 8; j++) acc[i][j] = 0.f;

    for (int k0 = 0; k0 < K; k0 += 8) {
        float4 a4 = *(const float4*)(A + (size_t)(row0 + aRow) * K + k0 + aCol);
        As[aCol + 0][aRow] = tf32r(a4.x);
        As[aCol + 1][aRow] = tf32r(a4.y);
        As[aCol + 2][aRow] = tf32r(a4.z);
        As[aCol + 3][aRow] = tf32r(a4.w);
        float4 b4 = *(const float4*)(Bm + (size_t)(k0 + bRow) * N + col0 + bCol);
        Bs[bRow][bCol + 0] = tf32r(b4.x);
        Bs[bRow][bCol + 1] = tf32r(b4.y);
        Bs[bRow][bCol + 2] = tf32r(b4.z);
        Bs[bRow][bCol + 3] = tf32r(b4.w);
        __syncthreads();
#pragma unroll
        for (int kk = 0; kk < 8; kk++) {
            float ra[8], rb[8];
#pragma unroll
            for (int i = 0; i < 8; i++) ra[i] = As[kk][ty * 8 + i];
#pragma unroll
            for (int j = 0; j < 8; j++) rb[j] = Bs[kk][tx * 8 + j];
#pragma unroll
            for (int i = 0; i < 8; i++)
#pragma unroll
                for (int j = 0; j < 8; j++)
                    acc[i][j] += ra[i] * rb[j];
        }
        __syncthreads();
    }
#pragma unroll
    for (int i = 0; i < 8; i++) {
        int r = row0 + ty * 8 + i;
#pragma unroll
        for (int j = 0; j < 8; j++) {
            int c = col0 + tx * 8 + j;
            Cm[(size_t)r * N + c] = acc[i][j] + bias[c];
        }
    }
}

// -------------------- layernorm: one warp per row (float4), 8 rows/block ---------------
__global__ __launch_bounds__(256) void ln_kernel(
    const float* __restrict__ x, const float* __restrict__ g,
    const float* __restrict__ b, float* __restrict__ out)
{
    const int row  = blockIdx.x * 8 + (threadIdx.x >> 5);
    const int lane = threadIdx.x & 31;
    const float4* xp = (const float4*)(x + (size_t)row * D_);
    const float4 a0 = xp[lane];
    const float4 a1 = xp[lane + 32];

    float s  = a0.x + a0.y + a0.z + a0.w + a1.x + a1.y + a1.z + a1.w;
    float s2 = a0.x*a0.x + a0.y*a0.y + a0.z*a0.z + a0.w*a0.w
             + a1.x*a1.x + a1.y*a1.y + a1.z*a1.z + a1.w*a1.w;
#pragma unroll
    for (int o = 16; o > 0; o >>= 1) {
        s  += __shfl_xor_sync(0xffffffffu, s,  o);
        s2 += __shfl_xor_sync(0xffffffffu, s2, o);
    }
    const float mean = s  * (1.f / 256.f);
    const float var  = s2 * (1.f / 256.f) - mean * mean;
    const float rs   = rsqrtf(var + 1e-5f);

    const float4 g0 = ((const float4*)g)[lane];
    const float4 g1 = ((const float4*)g)[lane + 32];
    const float4 b0 = ((const float4*)b)[lane];
    const float4 b1 = ((const float4*)b)[lane + 32];
    float4* op = (float4*)(out + (size_t)row * D_);
    op[lane]      = make_float4((a0.x-mean)*rs*g0.x + b0.x, (a0.y-mean)*rs*g0.y + b0.y,
                                (a0.z-mean)*rs*g0.z + b0.z, (a0.w-mean)*rs*g0.w + b0.w);
    op[lane + 32] = make_float4((a1.x-mean)*rs*g1.x + b1.x, (a1.y-mean)*rs*g1.y + b1.y,
                                (a1.z-mean)*rs*g1.z + b1.z, (a1.w-mean)*rs*g1.w + b1.w);
}

// -------------------- RoPE tables (double-precision trig of fp32-rounded angle) --------
__global__ void rope_tables_kernel()
{
    const int t = blockIdx.x * blockDim.x + threadIdx.x;   // C_*16 threads
    const int i = t & 15;
    const int c = t >> 4;
    const float invf = (float)(1.0 / pow(10000.0, (double)i / 16.0));
    const float angf = (float)c * invf;
    g_cos[t] = (float)cos((double)angf);
    g_sin[t] = (float)sin((double)angf);
}

// -------------------- RoPE in-place on q AND k ----------------------------------------
__global__ void rope_kernel(float* __restrict__ q, float* __restrict__ k)
{
    const int tid = blockIdx.x * blockDim.x + threadIdx.x;  // M_*H_*16 threads
    const int i = tid & 15;
    const int h = (tid >> 4) & 7;
    const int r = tid >> 7;
    const int c = r & (C_ - 1);
    const float cs = g_cos[c * 16 + i];
    const float sn = g_sin[c * 16 + i];
    const size_t off = (size_t)r * D_ + h * DH_;
    {
        float* p = q + off;
        const float t1 = p[i], t2 = p[i + 16];
        p[i]      = t1 * cs - t2 * sn;
        p[i + 16] = t1 * sn + t2 * cs;
    }
    {
        float* p = k + off;
        const float t1 = p[i], t2 = p[i + 16];
        p[i]      = t1 * cs - t2 * sn;
        p[i + 16] = t1 * sn + t2 * cs;
    }
}

// -------------------- windowed circular attention, TF32 einsum emulation --------------
// One warp per (b,h,q). lane = g*8+s: group g handles key j0+g, lane-quad s handles
// dims 4s..4s+3 via float4. 4 keys/iter, 3-shfl group reduction.
__global__ __launch_bounds__(128) void attn_kernel(
    const float* __restrict__ q, const float* __restrict__ k,
    const float* __restrict__ v, float* __restrict__ out)
{
    __shared__ float wbuf[4][64];
    const int warp = (blockIdx.x * blockDim.x + threadIdx.x) >> 5;  // (b,h,c)
    const int wib  = (threadIdx.x >> 5);
    const int lane = threadIdx.x & 31;
    const int g    = lane >> 3;
    const int s    = lane & 7;
    const int c = warp & (C_ - 1);
    const int h = (warp >> 11) & (H_ - 1);
    const int b = warp >> 14;
    const int qrow = b * C_ + c;
    const float scale = 0.17677669529663687f;                       // 1/sqrt(32)

    float4 q4 = ((const float4*)(q + (size_t)qrow * D_ + h * DH_))[s];
    q4.x = tf32r(q4.x); q4.y = tf32r(q4.y); q4.z = tf32r(q4.z); q4.w = tf32r(q4.w);

    // Phase 1: scores for 4 keys per iteration
#pragma unroll 3
    for (int j0 = 0; j0 < KTOK_; j0 += 4) {
        const int j = j0 + g;
        int kc = c - j; if (kc < 0) kc += C_;
        const float4 k4 = ((const float4*)(k + (size_t)(b * C_ + kc) * D_ + h * DH_))[s];
        float p = q4.x * tf32r(k4.x) + q4.y * tf32r(k4.y)
                + q4.z * tf32r(k4.z) + q4.w * tf32r(k4.w);
        p += __shfl_xor_sync(0xffffffffu, p, 1);
        p += __shfl_xor_sync(0xffffffffu, p, 2);
        p += __shfl_xor_sync(0xffffffffu, p, 4);
        if (s == 0) wbuf[wib][j] = p * scale;
    }
    __syncwarp();

    // Phase 2: max + denom (parallel over lanes)
    const float v1 = wbuf[wib][lane];
    const float v2 = (lane < KTOK_ - 32) ? wbuf[wib][lane + 32] : -INFINITY;
    float m = fmaxf(v1, v2);
#pragma unroll
    for (int o = 16; o > 0; o >>= 1) m = fmaxf(m, __shfl_xor_sync(0xffffffffu, m, o));
    const float p1 = __expf(v1 - m);
    const float p2 = (lane < KTOK_ - 32) ? __expf(v2 - m) : 0.f;
    wbuf[wib][lane] = p1;
    if (lane < KTOK_ - 32) wbuf[wib][lane + 32] = p2;
    float d = p1 + p2;
#pragma unroll
    for (int o = 16; o > 0; o >>= 1) d += __shfl_xor_sync(0xffffffffu, d, o);
    const float invd = 1.f / d;
    __syncwarp();

    // Phase 3: output accumulation, 4 keys per iteration
    float4 acc = make_float4(0.f, 0.f, 0.f, 0.f);
#pragma unroll 3
    for (int j0 = 0; j0 < KTOK_; j0 += 4) {
        const int j = j0 + g;
        int kc = c - j; if (kc < 0) kc += C_;
        const float4 v4 = ((const float4*)(v + (size_t)(b * C_ + kc) * D_ + h * DH_))[s];
        const float w = tf32r(wbuf[wib][j] * invd);
        acc.x += w * tf32r(v4.x);
        acc.y += w * tf32r(v4.y);
        acc.z += w * tf32r(v4.z);
        acc.w += w * tf32r(v4.w);
    }
#pragma unroll
    for (int o = 8; o <= 16; o <<= 1) {
        acc.x += __shfl_xor_sync(0xffffffffu, acc.x, o);
        acc.y += __shfl_xor_sync(0xffffffffu, acc.y, o);
        acc.z += __shfl_xor_sync(0xffffffffu, acc.z, o);
        acc.w += __shfl_xor_sync(0xffffffffu, acc.w, o);
    }
    if (g == 0)
        ((float4*)(out + (size_t)qrow * D_ + h * DH_))[s] = acc;
}

// -------------------- host orchestration --------------------
extern "C" void kernel_launch(void* const* d_in, const int* in_sizes, int n_in,
                              void* d_out, int out_size)
{
    const float* tok   = (const float*)d_in[0];
    const float* W_in  = (const float*)d_in[1];
    const float* b_in  = (const float*)d_in[2];
    const float* Wq    = (const float*)d_in[3];
    const float* bq    = (const float*)d_in[4];
    const float* Wk    = (const float*)d_in[5];
    const float* bk    = (const float*)d_in[6];
    const float* Wv    = (const float*)d_in[7];
    const float* bv    = (const float*)d_in[8];
    const float* Wo    = (const float*)d_in[9];
    const float* bo    = (const float*)d_in[10];
    const float* ln1g  = (const float*)d_in[11];
    const float* ln1b  = (const float*)d_in[12];
    const float* ln2g  = (const float*)d_in[13];
    const float* ln2b  = (const float*)d_in[14];
    const float* W1    = (const float*)d_in[15];
    const float* b1    = (const float*)d_in[16];
    const float* W2    = (const float*)d_in[17];
    const float* b2    = (const float*)d_in[18];
    const float* W_out = (const float*)d_in[19];
    const float* b_out = (const float*)d_in[20];
    float* out = (float*)d_out;

    float *x, *h, *q, *k, *v, *ao, *ff;
    cudaGetSymbolAddress((void**)&x,  g_x);
    cudaGetSymbolAddress((void**)&h,  g_h);
    cudaGetSymbolAddress((void**)&q,  g_q);
    cudaGetSymbolAddress((void**)&k,  g_k);
    cudaGetSymbolAddress((void**)&v,  g_v);
    cudaGetSymbolAddress((void**)&ao, g_ao);
    cudaGetSymbolAddress((void**)&ff, g_ff);

    // smem sizes:  big = 2*128*36*4 + 2*32*136*4 = 71680 ; small = 2*64*36*4 + 2*32*72*4 = 36864
    constexpr int SM_BIG   = 2 * 128 * 36 * 4 + 2 * 32 * 136 * 4;
    constexpr int SM_SMALL = 2 * 64  * 36 * 4 + 2 * 32 * 72  * 4;

    auto* kQKV = tgemm_kernel<64, 64, 2, 2, false, false, true>;
    auto* kRES = tgemm_kernel<64, 64, 2, 2, false, true,  false>;
    auto* kFF1 = tgemm_kernel<128, 128, 2, 4, true,  false, false>;
    auto* kOUT = tgemm_kernel<128, 128, 2, 4, false, false, false>;
    cudaFuncSetAttribute(kQKV, cudaFuncAttributeMaxDynamicSharedMemorySize, SM_SMALL);
    cudaFuncSetAttribute(kRES, cudaFuncAttributeMaxDynamicSharedMemorySize, SM_SMALL);
    cudaFuncSetAttribute(kFF1, cudaFuncAttributeMaxDynamicSharedMemorySize, SM_BIG);
    cudaFuncSetAttribute(kOUT, cudaFuncAttributeMaxDynamicSharedMemorySize, SM_BIG);

    const dim3 gQKV(D_ / 64, M_ / 64, 3);     // (4, 64, 3)
    const dim3 gRES(D_ / 64, M_ / 64);        // (4, 64)
    const dim3 gFF (FF_ / 128, M_ / 128);     // (16, 32)
    const dim3 gO  (NOUT_ / 128, M_ / 128);   // (128, 32)

    rope_tables_kernel<<<(C_ * 16) / 256, 256>>>();

    // x = tok @ W_in + b_in   (K = 8, FFMA path)
    embed_kernel<<<dim3(D_ / 128, M_ / 128), 256>>>(tok, W_in, b_in, x, M_, D_, 8);

    for (int l = 0; l < L_; l++) {
        ln_kernel<<<M_ / 8, 256>>>(x, ln1g + l * D_, ln1b + l * D_, h);

        kQKV<<<gQKV, 128, SM_SMALL>>>(h,
            Wq + (size_t)l * D_ * D_, bq + l * D_, q, nullptr, D_, D_,
            Wk + (size_t)l * D_ * D_, bk + l * D_, k,
            Wv + (size_t)l * D_ * D_, bv + l * D_, v);

        rope_kernel<<<(M_ * H_ * 16) / 256, 256>>>(q, k);

        attn_kernel<<<(B_ * H_ * C_ * 32) / 128, 128>>>(q, k, v, ao);

        // x = x + ao @ Wo + bo
        kRES<<<gRES, 128, SM_SMALL>>>(ao,
            Wo + (size_t)l * D_ * D_, bo + l * D_, x, x, D_, D_,
            nullptr, nullptr, nullptr, nullptr, nullptr, nullptr);

        ln_kernel<<<M_ / 8, 256>>>(x, ln2g + l * D_, ln2b + l * D_, h);

        // ff = relu(h @ W1 + b1)
        kFF1<<<gFF, 256, SM_BIG>>>(h,
            W1 + (size_t)l * D_ * FF_, b1 + l * FF_, ff, nullptr, FF_, D_,
            nullptr, nullptr, nullptr, nullptr, nullptr, nullptr);
        // x = x + ff @ W2 + b2
        kRES<<<gRES, 128, SM_SMALL>>>(ff,
            W2 + (size_t)l * FF_ * D_, b2 + l * D_, x, x, D_, FF_,
            nullptr, nullptr, nullptr, nullptr, nullptr, nullptr);
    }

    // out = x @ W_out + b_out
    kOUT<<<gO, 256, SM_BIG>>>(x,
        W_out, b_out, out, nullptr, NOUT_, D_,
        nullptr, nullptr, nullptr, nullptr, nullptr, nullptr);
}

// round 7
// speedup vs baseline: 4.7432x; 1.1467x over previous
#include <cuda_runtime.h>
#include <math.h>
#include <stdint.h>

// Problem constants (fixed by setup_inputs)
#define B_      2
#define C_      2048
#define D_      256
#define H_      8
#define L_      4
#define FF_     2048
#define DH_     32
#define NOUT_   16384
#define M_      (B_ * C_)      // 4096
#define KTOK_   60

// -------------------- scratch --------------------
__device__ float g_x [M_ * D_];
__device__ float g_h [M_ * D_];
__device__ float g_q [M_ * D_];
__device__ float g_k [M_ * D_];
__device__ float g_v [M_ * D_];
__device__ float g_ao[M_ * D_];
__device__ float g_ff[M_ * FF_];
__device__ float g_cos[C_ * 16];
__device__ float g_sin[C_ * 16];
// pre-quantized (tf32) weights
__device__ float g_wq[L_ * D_ * D_];
__device__ float g_wk[L_ * D_ * D_];
__device__ float g_wv[L_ * D_ * D_];
__device__ float g_wo[L_ * D_ * D_];
__device__ float g_w1[L_ * D_ * FF_];
__device__ float g_w2[L_ * FF_ * D_];
__device__ float g_wout[D_ * NOUT_];

// TF32 input quantization (round-to-nearest-away), matching cuBLAS/XLA TF32 matmuls.
__device__ __forceinline__ float tf32r(float x) {
    float r;
    asm("cvt.rna.tf32.f32 %0, %1;" : "=f"(r) : "f"(x));
    return r;
}

__device__ __forceinline__ void cp16(uint32_t saddr, const float* gptr) {
    asm volatile("cp.async.cg.shared.global [%0], [%1], 16;" :: "r"(saddr), "l"(gptr));
}
__device__ __forceinline__ void cp_commit() {
    asm volatile("cp.async.commit_group;" ::: "memory");
}
template<int N>
__device__ __forceinline__ void cp_wait() {
    asm volatile("cp.async.wait_group %0;" :: "n"(N) : "memory");
}

// -------------------- tf32-quantizing float4 copy (weights / activations) --------------
__global__ void qcopy_kernel(const float* __restrict__ src, float* __restrict__ dst, int n4)
{
    const int i = blockIdx.x * blockDim.x + threadIdx.x;
    if (i < n4) {
        float4 a = ((const float4*)src)[i];
        a.x = tf32r(a.x); a.y = tf32r(a.y); a.z = tf32r(a.z); a.w = tf32r(a.w);
        ((float4*)dst)[i] = a;
    }
}

// ==================== TF32 tensor-core GEMM, double-buffered cp.async ====================
// All inputs PRE-QUANTIZED to tf32 values. C = A@B + bias [+res] [relu] [tf32-out].
template<int BM, int BN, int WM_, int WN_, bool RELU, bool RES, bool QKV3, bool QOUT>
__global__ void tgemm_kernel(
    const float* __restrict__ A,
    const float* __restrict__ B0, const float* __restrict__ bias0, float* __restrict__ C0,
    const float* __restrict__ res,
    int N, int K,
    const float* B1, const float* bias1, float* C1,
    const float* B2, const float* bias2, float* C2)
{
    constexpr int THREADS = WM_ * WN_ * 32;
    constexpr int AST = 36;         // A smem stride (BK+4)
    constexpr int BST = BN + 8;     // B smem stride
    constexpr int FM  = (BM / WM_) / 16;
    constexpr int FN  = (BN / WN_) / 8;

    extern __shared__ float smem[];
    float* As = smem;                     // [2][BM][AST]
    float* Bs = smem + 2 * BM * AST;      // [2][32][BST]

    const float* Bm = B0;  const float* bias = bias0;  float* Cm = C0;
    if (QKV3) {
        if (blockIdx.z == 1)      { Bm = B1; bias = bias1; Cm = C1; }
        else if (blockIdx.z == 2) { Bm = B2; bias = bias2; Cm = C2; }
    }

    const int tid  = threadIdx.x;
    const int warp = tid >> 5;
    const int lane = tid & 31;
    const int wm   = warp / WN_;
    const int wn   = warp % WN_;
    const int gid  = lane >> 2;
    const int tid4 = lane & 3;

    const int row0 = blockIdx.y * BM;
    const int col0 = blockIdx.x * BN;

    float acc[FM][FN][4];
#pragma unroll
    for (int i = 0; i < FM; i++)
#pragma unroll
        for (int j = 0; j < FN; j++)
#pragma unroll
            for (int t = 0; t < 4; t++) acc[i][j][t] = 0.f;

    const int nk = K >> 5;

    // stage-issue lambda (A: BM x 32, B: 32 x BN)
    auto issue = [&](int t, int buf) {
        const int k0 = t << 5;
        float* Ad = As + buf * BM * AST;
        float* Bd = Bs + buf * 32 * BST;
#pragma unroll
        for (int i = 0; i < (BM * 8) / THREADS; i++) {
            const int idx = tid + i * THREADS;
            const int r   = idx >> 3;
            const int k4  = (idx & 7) * 4;
            cp16((uint32_t)__cvta_generic_to_shared(Ad + r * AST + k4),
                 A + (size_t)(row0 + r) * K + k0 + k4);
        }
#pragma unroll
        for (int i = 0; i < (BN * 8) / THREADS; i++) {
            const int idx = tid + i * THREADS;
            const int kr  = idx / (BN / 4);
            const int c4  = (idx % (BN / 4)) * 4;
            cp16((uint32_t)__cvta_generic_to_shared(Bd + kr * BST + c4),
                 Bm + (size_t)(k0 + kr) * N + col0 + c4);
        }
        cp_commit();
    };

    issue(0, 0);
    for (int t = 0; t < nk; t++) {
        if (t + 1 < nk) { issue(t + 1, (t + 1) & 1); cp_wait<1>(); }
        else            { cp_wait<0>(); }
        __syncthreads();

        const float* Ab = As + (t & 1) * BM * AST;
        const float* Bb = Bs + (t & 1) * 32 * BST;
#pragma unroll
        for (int kk = 0; kk < 32; kk += 8) {
            uint32_t af[FM][4];
#pragma unroll
            for (int mf = 0; mf < FM; mf++) {
                const int ar = wm * (BM / WM_) + mf * 16 + gid;
                af[mf][0] = __float_as_uint(Ab[(ar    ) * AST + kk + tid4    ]);
                af[mf][1] = __float_as_uint(Ab[(ar + 8) * AST + kk + tid4    ]);
                af[mf][2] = __float_as_uint(Ab[(ar    ) * AST + kk + tid4 + 4]);
                af[mf][3] = __float_as_uint(Ab[(ar + 8) * AST + kk + tid4 + 4]);
            }
            uint32_t bf[FN][2];
#pragma unroll
            for (int nf = 0; nf < FN; nf++) {
                const int bc = wn * (BN / WN_) + nf * 8 + gid;
                bf[nf][0] = __float_as_uint(Bb[(kk + tid4    ) * BST + bc]);
                bf[nf][1] = __float_as_uint(Bb[(kk + tid4 + 4) * BST + bc]);
            }
#pragma unroll
            for (int mf = 0; mf < FM; mf++)
#pragma unroll
                for (int nf = 0; nf < FN; nf++) {
                    asm volatile(
                        "mma.sync.aligned.m16n8k8.row.col.f32.tf32.tf32.f32 "
                        "{%0,%1,%2,%3}, {%4,%5,%6,%7}, {%8,%9}, {%0,%1,%2,%3};"
                        : "+f"(acc[mf][nf][0]), "+f"(acc[mf][nf][1]),
                          "+f"(acc[mf][nf][2]), "+f"(acc[mf][nf][3])
                        : "r"(af[mf][0]), "r"(af[mf][1]), "r"(af[mf][2]), "r"(af[mf][3]),
                          "r"(bf[nf][0]), "r"(bf[nf][1]));
                }
        }
        __syncthreads();
    }

    // Epilogue
#pragma unroll
    for (int mf = 0; mf < FM; mf++) {
        const int r = row0 + wm * (BM / WM_) + mf * 16 + gid;
#pragma unroll
        for (int nf = 0; nf < FN; nf++) {
            const int c = col0 + wn * (BN / WN_) + nf * 8 + tid4 * 2;
            float v0 = acc[mf][nf][0] + bias[c];
            float v1 = acc[mf][nf][1] + bias[c + 1];
            float v2 = acc[mf][nf][2] + bias[c];
            float v3 = acc[mf][nf][3] + bias[c + 1];
            if (RES) {
                const float2 r0 = *(const float2*)(res + (size_t)r * N + c);
                const float2 r1 = *(const float2*)(res + (size_t)(r + 8) * N + c);
                v0 += r0.x; v1 += r0.y; v2 += r1.x; v3 += r1.y;
            }
            if (RELU) {
                v0 = fmaxf(v0, 0.f); v1 = fmaxf(v1, 0.f);
                v2 = fmaxf(v2, 0.f); v3 = fmaxf(v3, 0.f);
            }
            if (QOUT) {
                v0 = tf32r(v0); v1 = tf32r(v1); v2 = tf32r(v2); v3 = tf32r(v3);
            }
            *(float2*)(Cm + (size_t)r * N + c)       = make_float2(v0, v1);
            *(float2*)(Cm + (size_t)(r + 8) * N + c) = make_float2(v2, v3);
        }
    }
}

// -------------------- FFMA GEMM for the K=8 embed only --------------------
__global__ __launch_bounds__(256) void embed_kernel(
    const float* __restrict__ A, const float* __restrict__ Bm,
    const float* __restrict__ bias, float* __restrict__ Cm, int M, int N, int K)
{
    __shared__ float As[8][128];
    __shared__ float Bs[8][128];
    const int tid  = threadIdx.x;
    const int tx   = tid & 15;
    const int ty   = tid >> 4;
    const int row0 = blockIdx.y * 128;
    const int col0 = blockIdx.x * 128;
    const int aRow = tid >> 1;
    const int aCol = (tid & 1) * 4;
    const int bRow = tid >> 5;
    const int bCol = (tid & 31) * 4;

    float acc[8][8];
#pragma unroll
    for (int i = 0; i < 8; i++)
#pragma unroll
        for (int j = 0; j < 8; j++) acc[i][j] = 0.f;

    for (int k0 = 0; k0 < K; k0 += 8) {
        float4 a4 = *(const float4*)(A + (size_t)(row0 + aRow) * K + k0 + aCol);
        As[aCol + 0][aRow] = tf32r(a4.x);
        As[aCol + 1][aRow] = tf32r(a4.y);
        As[aCol + 2][aRow] = tf32r(a4.z);
        As[aCol + 3][aRow] = tf32r(a4.w);
        float4 b4 = *(const float4*)(Bm + (size_t)(k0 + bRow) * N + col0 + bCol);
        Bs[bRow][bCol + 0] = tf32r(b4.x);
        Bs[bRow][bCol + 1] = tf32r(b4.y);
        Bs[bRow][bCol + 2] = tf32r(b4.z);
        Bs[bRow][bCol + 3] = tf32r(b4.w);
        __syncthreads();
#pragma unroll
        for (int kk = 0; kk < 8; kk++) {
            float ra[8], rb[8];
#pragma unroll
            for (int i = 0; i < 8; i++) ra[i] = As[kk][ty * 8 + i];
#pragma unroll
            for (int j = 0; j < 8; j++) rb[j] = Bs[kk][tx * 8 + j];
#pragma unroll
            for (int i = 0; i < 8; i++)
#pragma unroll
                for (int j = 0; j < 8; j++)
                    acc[i][j] += ra[i] * rb[j];
        }
        __syncthreads();
    }
#pragma unroll
    for (int i = 0; i < 8; i++) {
        int r = row0 + ty * 8 + i;
#pragma unroll
        for (int j = 0; j < 8; j++) {
            int c = col0 + tx * 8 + j;
            Cm[(size_t)r * N + c] = acc[i][j] + bias[c];
        }
    }
}

// -------------------- layernorm (warp/row, float4); OUTPUT IS TF32-QUANTIZED -----------
// h feeds only GEMM A-sides, so quantizing here == quantizing at GEMM read.
__global__ __launch_bounds__(256) void ln_kernel(
    const float* __restrict__ x, const float* __restrict__ g,
    const float* __restrict__ b, float* __restrict__ out)
{
    const int row  = blockIdx.x * 8 + (threadIdx.x >> 5);
    const int lane = threadIdx.x & 31;
    const float4* xp = (const float4*)(x + (size_t)row * D_);
    const float4 a0 = xp[lane];
    const float4 a1 = xp[lane + 32];

    float s  = a0.x + a0.y + a0.z + a0.w + a1.x + a1.y + a1.z + a1.w;
    float s2 = a0.x*a0.x + a0.y*a0.y + a0.z*a0.z + a0.w*a0.w
             + a1.x*a1.x + a1.y*a1.y + a1.z*a1.z + a1.w*a1.w;
#pragma unroll
    for (int o = 16; o > 0; o >>= 1) {
        s  += __shfl_xor_sync(0xffffffffu, s,  o);
        s2 += __shfl_xor_sync(0xffffffffu, s2, o);
    }
    const float mean = s  * (1.f / 256.f);
    const float var  = s2 * (1.f / 256.f) - mean * mean;
    const float rs   = rsqrtf(var + 1e-5f);

    const float4 g0 = ((const float4*)g)[lane];
    const float4 g1 = ((const float4*)g)[lane + 32];
    const float4 b0 = ((const float4*)b)[lane];
    const float4 b1 = ((const float4*)b)[lane + 32];
    float4* op = (float4*)(out + (size_t)row * D_);
    op[lane]      = make_float4(tf32r((a0.x-mean)*rs*g0.x + b0.x), tf32r((a0.y-mean)*rs*g0.y + b0.y),
                                tf32r((a0.z-mean)*rs*g0.z + b0.z), tf32r((a0.w-mean)*rs*g0.w + b0.w));
    op[lane + 32] = make_float4(tf32r((a1.x-mean)*rs*g1.x + b1.x), tf32r((a1.y-mean)*rs*g1.y + b1.y),
                                tf32r((a1.z-mean)*rs*g1.z + b1.z), tf32r((a1.w-mean)*rs*g1.w + b1.w));
}

// -------------------- RoPE tables (double-precision trig of fp32-rounded angle) --------
__global__ void rope_tables_kernel()
{
    const int t = blockIdx.x * blockDim.x + threadIdx.x;   // C_*16 threads
    const int i = t & 15;
    const int c = t >> 4;
    const float invf = (float)(1.0 / pow(10000.0, (double)i / 16.0));
    const float angf = (float)c * invf;
    g_cos[t] = (float)cos((double)angf);
    g_sin[t] = (float)sin((double)angf);
}

// -------------------- RoPE in-place on q AND k; OUTPUT IS TF32-QUANTIZED ---------------
// Rope computed on fp32 inputs (matching reference), quantized at write since the
// rope'd q/k feed only the score einsum.
__global__ void rope_kernel(float* __restrict__ q, float* __restrict__ k)
{
    const int tid = blockIdx.x * blockDim.x + threadIdx.x;  // M_*H_*16 threads
    const int i = tid & 15;
    const int h = (tid >> 4) & 7;
    const int r = tid >> 7;
    const int c = r & (C_ - 1);
    const float cs = g_cos[c * 16 + i];
    const float sn = g_sin[c * 16 + i];
    const size_t off = (size_t)r * D_ + h * DH_;
    {
        float* p = q + off;
        const float t1 = p[i], t2 = p[i + 16];
        p[i]      = tf32r(t1 * cs - t2 * sn);
        p[i + 16] = tf32r(t1 * sn + t2 * cs);
    }
    {
        float* p = k + off;
        const float t1 = p[i], t2 = p[i + 16];
        p[i]      = tf32r(t1 * cs - t2 * sn);
        p[i + 16] = tf32r(t1 * sn + t2 * cs);
    }
}

// -------------------- windowed circular attention --------------------
// q/k already tf32-quantized by rope. v quantized at read; output quantized at write
// (feeds only the Wo GEMM A-side).
__global__ __launch_bounds__(128) void attn_kernel(
    const float* __restrict__ q, const float* __restrict__ k,
    const float* __restrict__ v, float* __restrict__ out)
{
    __shared__ float wbuf[4][64];
    const int warp = (blockIdx.x * blockDim.x + threadIdx.x) >> 5;  // (b,h,c)
    const int wib  = (threadIdx.x >> 5);
    const int lane = threadIdx.x & 31;
    const int g    = lane >> 3;
    const int s    = lane & 7;
    const int c = warp & (C_ - 1);
    const int h = (warp >> 11) & (H_ - 1);
    const int b = warp >> 14;
    const int qrow = b * C_ + c;
    const float scale = 0.17677669529663687f;                       // 1/sqrt(32)

    const float4 q4 = ((const float4*)(q + (size_t)qrow * D_ + h * DH_))[s];

    // Phase 1: scores for 4 keys per iteration
#pragma unroll 3
    for (int j0 = 0; j0 < KTOK_; j0 += 4) {
        const int j = j0 + g;
        int kc = c - j; if (kc < 0) kc += C_;
        const float4 k4 = ((const float4*)(k + (size_t)(b * C_ + kc) * D_ + h * DH_))[s];
        float p = q4.x * k4.x + q4.y * k4.y + q4.z * k4.z + q4.w * k4.w;
        p += __shfl_xor_sync(0xffffffffu, p, 1);
        p += __shfl_xor_sync(0xffffffffu, p, 2);
        p += __shfl_xor_sync(0xffffffffu, p, 4);
        if (s == 0) wbuf[wib][j] = p * scale;
    }
    __syncwarp();

    // Phase 2: max + denom (parallel over lanes)
    const float v1 = wbuf[wib][lane];
    const float v2 = (lane < KTOK_ - 32) ? wbuf[wib][lane + 32] : -INFINITY;
    float m = fmaxf(v1, v2);
#pragma unroll
    for (int o = 16; o > 0; o >>= 1) m = fmaxf(m, __shfl_xor_sync(0xffffffffu, m, o));
    const float p1 = __expf(v1 - m);
    const float p2 = (lane < KTOK_ - 32) ? __expf(v2 - m) : 0.f;
    wbuf[wib][lane] = p1;
    if (lane < KTOK_ - 32) wbuf[wib][lane + 32] = p2;
    float d = p1 + p2;
#pragma unroll
    for (int o = 16; o > 0; o >>= 1) d += __shfl_xor_sync(0xffffffffu, d, o);
    const float invd = 1.f / d;
    __syncwarp();

    // Phase 3: output accumulation, 4 keys per iteration
    float4 acc = make_float4(0.f, 0.f, 0.f, 0.f);
#pragma unroll 3
    for (int j0 = 0; j0 < KTOK_; j0 += 4) {
        const int j = j0 + g;
        int kc = c - j; if (kc < 0) kc += C_;
        const float4 v4 = ((const float4*)(v + (size_t)(b * C_ + kc) * D_ + h * DH_))[s];
        const float w = tf32r(wbuf[wib][j] * invd);
        acc.x += w * tf32r(v4.x);
        acc.y += w * tf32r(v4.y);
        acc.z += w * tf32r(v4.z);
        acc.w += w * tf32r(v4.w);
    }
#pragma unroll
    for (int o = 8; o <= 16; o <<= 1) {
        acc.x += __shfl_xor_sync(0xffffffffu, acc.x, o);
        acc.y += __shfl_xor_sync(0xffffffffu, acc.y, o);
        acc.z += __shfl_xor_sync(0xffffffffu, acc.z, o);
        acc.w += __shfl_xor_sync(0xffffffffu, acc.w, o);
    }
    if (g == 0)
        ((float4*)(out + (size_t)qrow * D_ + h * DH_))[s] =
            make_float4(tf32r(acc.x), tf32r(acc.y), tf32r(acc.z), tf32r(acc.w));
}

// -------------------- host orchestration --------------------
extern "C" void kernel_launch(void* const* d_in, const int* in_sizes, int n_in,
                              void* d_out, int out_size)
{
    const float* tok   = (const float*)d_in[0];
    const float* W_in  = (const float*)d_in[1];
    const float* b_in  = (const float*)d_in[2];
    const float* Wq    = (const float*)d_in[3];
    const float* bq    = (const float*)d_in[4];
    const float* Wk    = (const float*)d_in[5];
    const float* bk    = (const float*)d_in[6];
    const float* Wv    = (const float*)d_in[7];
    const float* bv    = (const float*)d_in[8];
    const float* Wo    = (const float*)d_in[9];
    const float* bo    = (const float*)d_in[10];
    const float* ln1g  = (const float*)d_in[11];
    const float* ln1b  = (const float*)d_in[12];
    const float* ln2g  = (const float*)d_in[13];
    const float* ln2b  = (const float*)d_in[14];
    const float* W1    = (const float*)d_in[15];
    const float* b1    = (const float*)d_in[16];
    const float* W2    = (const float*)d_in[17];
    const float* b2    = (const float*)d_in[18];
    const float* W_out = (const float*)d_in[19];
    const float* b_out = (const float*)d_in[20];
    float* out = (float*)d_out;

    float *x, *h, *q, *k, *v, *ao, *ff;
    float *wq, *wk, *wv, *wo, *w1, *w2, *wout;
    cudaGetSymbolAddress((void**)&x,  g_x);
    cudaGetSymbolAddress((void**)&h,  g_h);
    cudaGetSymbolAddress((void**)&q,  g_q);
    cudaGetSymbolAddress((void**)&k,  g_k);
    cudaGetSymbolAddress((void**)&v,  g_v);
    cudaGetSymbolAddress((void**)&ao, g_ao);
    cudaGetSymbolAddress((void**)&ff, g_ff);
    cudaGetSymbolAddress((void**)&wq, g_wq);
    cudaGetSymbolAddress((void**)&wk, g_wk);
    cudaGetSymbolAddress((void**)&wv, g_wv);
    cudaGetSymbolAddress((void**)&wo, g_wo);
    cudaGetSymbolAddress((void**)&w1, g_w1);
    cudaGetSymbolAddress((void**)&w2, g_w2);
    cudaGetSymbolAddress((void**)&wout, g_wout);

    constexpr int SM_BIG   = 2 * 128 * 36 * 4 + 2 * 32 * 136 * 4;   // 71680
    constexpr int SM_SMALL = 2 * 64  * 36 * 4 + 2 * 32 * 72  * 4;   // 36864

    auto* kQKV = tgemm_kernel<64, 64, 2, 2, false, false, true,  false>;
    auto* kRES = tgemm_kernel<64, 64, 2, 2, false, true,  false, false>;
    auto* kFF1 = tgemm_kernel<128, 128, 2, 4, true,  false, false, true>;
    auto* kOUT = tgemm_kernel<128, 128, 2, 4, false, false, false, false>;
    cudaFuncSetAttribute(kQKV, cudaFuncAttributeMaxDynamicSharedMemorySize, SM_SMALL);
    cudaFuncSetAttribute(kRES, cudaFuncAttributeMaxDynamicSharedMemorySize, SM_SMALL);
    cudaFuncSetAttribute(kFF1, cudaFuncAttributeMaxDynamicSharedMemorySize, SM_BIG);
    cudaFuncSetAttribute(kOUT, cudaFuncAttributeMaxDynamicSharedMemorySize, SM_BIG);

    const dim3 gQKV(D_ / 64, M_ / 64, 3);     // (4, 64, 3)
    const dim3 gRES(D_ / 64, M_ / 64);        // (4, 64)
    const dim3 gFF (FF_ / 128, M_ / 128);     // (16, 32)
    const dim3 gO  (NOUT_ / 128, M_ / 128);   // (128, 32)

    // Pre-quantize all weights to tf32 values (once per run; graph replays it).
    constexpr int NQKVO4 = (L_ * D_ * D_) / 4;     // 65536
    constexpr int NW124  = (L_ * D_ * FF_) / 4;    // 524288
    constexpr int NWOUT4 = (D_ * NOUT_) / 4;       // 1048576
    qcopy_kernel<<<NQKVO4 / 256, 256>>>(Wq, wq, NQKVO4);
    qcopy_kernel<<<NQKVO4 / 256, 256>>>(Wk, wk, NQKVO4);
    qcopy_kernel<<<NQKVO4 / 256, 256>>>(Wv, wv, NQKVO4);
    qcopy_kernel<<<NQKVO4 / 256, 256>>>(Wo, wo, NQKVO4);
    qcopy_kernel<<<NW124  / 256, 256>>>(W1, w1, NW124);
    qcopy_kernel<<<NW124  / 256, 256>>>(W2, w2, NW124);
    qcopy_kernel<<<NWOUT4 / 256, 256>>>(W_out, wout, NWOUT4);

    rope_tables_kernel<<<(C_ * 16) / 256, 256>>>();

    // x = tok @ W_in + b_in   (K = 8, FFMA path; x stays fp32)
    embed_kernel<<<dim3(D_ / 128, M_ / 128), 256>>>(tok, W_in, b_in, x, M_, D_, 8);

    for (int l = 0; l < L_; l++) {
        ln_kernel<<<M_ / 8, 256>>>(x, ln1g + l * D_, ln1b + l * D_, h);

        kQKV<<<gQKV, 128, SM_SMALL>>>(h,
            wq + (size_t)l * D_ * D_, bq + l * D_, q, nullptr, D_, D_,
            wk + (size_t)l * D_ * D_, bk + l * D_, k,
            wv + (size_t)l * D_ * D_, bv + l * D_, v);

        rope_kernel<<<(M_ * H_ * 16) / 256, 256>>>(q, k);

        attn_kernel<<<(B_ * H_ * C_ * 32) / 128, 128>>>(q, k, v, ao);

        // x = x + ao @ Wo + bo   (x stays fp32)
        kRES<<<gRES, 128, SM_SMALL>>>(ao,
            wo + (size_t)l * D_ * D_, bo + l * D_, x, x, D_, D_,
            nullptr, nullptr, nullptr, nullptr, nullptr, nullptr);

        ln_kernel<<<M_ / 8, 256>>>(x, ln2g + l * D_, ln2b + l * D_, h);

        // ff = tf32(relu(h @ W1 + b1))
        kFF1<<<gFF, 256, SM_BIG>>>(h,
            w1 + (size_t)l * D_ * FF_, b1 + l * FF_, ff, nullptr, FF_, D_,
            nullptr, nullptr, nullptr, nullptr, nullptr, nullptr);
        // x = x + ff @ W2 + b2
        kRES<<<gRES, 128, SM_SMALL>>>(ff,
            w2 + (size_t)l * FF_ * D_, b2 + l * D_, x, x, D_, FF_,
            nullptr, nullptr, nullptr, nullptr, nullptr, nullptr);
    }

    // xq = tf32(x) ; out = xq @ W_out + b_out   (reuse q buffer as xq)
    qcopy_kernel<<<(M_ * D_ / 4) / 256, 256>>>(x, q, M_ * D_ / 4);
    kOUT<<<gO, 256, SM_BIG>>>(q,
        wout, b_out, out, nullptr, NOUT_, D_,
        nullptr, nullptr, nullptr, nullptr, nullptr, nullptr);
}

// round 9
// speedup vs baseline: 4.8221x; 1.0166x over previous
#include <cuda_runtime.h>
#include <math.h>
#include <stdint.h>

// Problem constants (fixed by setup_inputs)
#define B_      2
#define C_      2048
#define D_      256
#define H_      8
#define L_      4
#define FF_     2048
#define DH_     32
#define NOUT_   16384
#define M_      (B_ * C_)      // 4096
#define KTOK_   60

// -------------------- scratch --------------------
__device__ float g_x [M_ * D_];
__device__ float g_h [M_ * D_];
__device__ float g_q [M_ * D_];
__device__ float g_k [M_ * D_];
__device__ float g_v [M_ * D_];
__device__ float g_ao[M_ * D_];
__device__ float g_ff[M_ * FF_];
__device__ float g_cos[C_ * 16];
__device__ float g_sin[C_ * 16];
// pre-quantized (tf32) weights
__device__ float g_wq[L_ * D_ * D_];
__device__ float g_wk[L_ * D_ * D_];
__device__ float g_wv[L_ * D_ * D_];
__device__ float g_wo[L_ * D_ * D_];
__device__ float g_w1[L_ * D_ * FF_];
__device__ float g_w2[L_ * FF_ * D_];
__device__ float g_wout[D_ * NOUT_];

// TF32 input quantization (round-to-nearest-away), matching cuBLAS/XLA TF32 matmuls.
__device__ __forceinline__ float tf32r(float x) {
    float r;
    asm("cvt.rna.tf32.f32 %0, %1;" : "=f"(r) : "f"(x));
    return r;
}

__device__ __forceinline__ void cp16(uint32_t saddr, const float* gptr) {
    asm volatile("cp.async.cg.shared.global [%0], [%1], 16;" :: "r"(saddr), "l"(gptr));
}
__device__ __forceinline__ void cp_commit() {
    asm volatile("cp.async.commit_group;" ::: "memory");
}
template<int N>
__device__ __forceinline__ void cp_wait() {
    asm volatile("cp.async.wait_group %0;" :: "n"(N) : "memory");
}

// -------------------- single fused weight-prequant kernel (float4 granularity) ---------
// segment cumsum in float4 units
#define SEG_A  (L_ * D_ * D_ / 4)        // 65536 per qkv/o weight
#define SEG_W  (L_ * D_ * FF_ / 4)       // 524288 per w1/w2
#define SEG_O  (D_ * NOUT_ / 4)          // 1048576
#define PQ_TOTAL (4 * SEG_A + 2 * SEG_W + SEG_O)   // 2359296

__global__ void prequant_kernel(
    const float* __restrict__ Wq, const float* __restrict__ Wk,
    const float* __restrict__ Wv, const float* __restrict__ Wo,
    const float* __restrict__ W1, const float* __restrict__ W2,
    const float* __restrict__ Wout)
{
    int i = blockIdx.x * blockDim.x + threadIdx.x;
    if (i >= PQ_TOTAL) return;
    const float* src; float* dst;
    if      (i < 1 * SEG_A)                     { src = Wq;  dst = g_wq;   i -= 0 * SEG_A; }
    else if (i < 2 * SEG_A)                     { src = Wk;  dst = g_wk;   i -= 1 * SEG_A; }
    else if (i < 3 * SEG_A)                     { src = Wv;  dst = g_wv;   i -= 2 * SEG_A; }
    else if (i < 4 * SEG_A)                     { src = Wo;  dst = g_wo;   i -= 3 * SEG_A; }
    else if (i < 4 * SEG_A + SEG_W)             { src = W1;  dst = g_w1;   i -= 4 * SEG_A; }
    else if (i < 4 * SEG_A + 2 * SEG_W)         { src = W2;  dst = g_w2;   i -= 4 * SEG_A + SEG_W; }
    else                                        { src = Wout;dst = g_wout; i -= 4 * SEG_A + 2 * SEG_W; }
    float4 a = ((const float4*)src)[i];
    a.x = tf32r(a.x); a.y = tf32r(a.y); a.z = tf32r(a.z); a.w = tf32r(a.w);
    ((float4*)dst)[i] = a;
}

// tf32-quantizing float4 copy (activation x -> xq before out GEMM)
__global__ void qcopy_kernel(const float* __restrict__ src, float* __restrict__ dst, int n4)
{
    const int i = blockIdx.x * blockDim.x + threadIdx.x;
    if (i < n4) {
        float4 a = ((const float4*)src)[i];
        a.x = tf32r(a.x); a.y = tf32r(a.y); a.z = tf32r(a.z); a.w = tf32r(a.w);
        ((float4*)dst)[i] = a;
    }
}

// ==================== TF32 tensor-core GEMM, double-buffered cp.async ====================
// All inputs PRE-QUANTIZED tf32 values. C = A@B [+bias] [+res] [relu] [tf32-out].
// KSPLIT2: blockIdx.z in {0,1} selects K-half (A col-offset z*K, B ptr B0/B1, C ptr C0/C1).
template<int BM, int BN, int WM_, int WN_, bool RELU, bool RES, bool QKV3, bool QOUT,
         bool BIASF, bool KSPLIT2>
__global__ void tgemm_kernel(
    const float* __restrict__ A,
    const float* __restrict__ B0, const float* __restrict__ bias0, float* __restrict__ C0,
    const float* __restrict__ res,
    int N, int K, int lda,
    const float* B1, const float* bias1, float* C1,
    const float* B2, const float* bias2, float* C2)
{
    constexpr int THREADS = WM_ * WN_ * 32;
    constexpr int AST = 36;         // A smem stride (BK+4)
    constexpr int BST = BN + 8;     // B smem stride
    constexpr int FM  = (BM / WM_) / 16;
    constexpr int FN  = (BN / WN_) / 8;

    extern __shared__ float smem[];
    float* As = smem;                     // [2][BM][AST]
    float* Bs = smem + 2 * BM * AST;      // [2][32][BST]

    const float* Ap = A;
    const float* Bm = B0;  const float* bias = bias0;  float* Cm = C0;
    if (QKV3) {
        if (blockIdx.z == 1)      { Bm = B1; bias = bias1; Cm = C1; }
        else if (blockIdx.z == 2) { Bm = B2; bias = bias2; Cm = C2; }
    }
    if (KSPLIT2) {
        if (blockIdx.z == 1) { Ap = A + K; Bm = B1; Cm = C1; }
    }

    const int tid  = threadIdx.x;
    const int warp = tid >> 5;
    const int lane = tid & 31;
    const int wm   = warp / WN_;
    const int wn   = warp % WN_;
    const int gid  = lane >> 2;
    const int tid4 = lane & 3;

    const int row0 = blockIdx.y * BM;
    const int col0 = blockIdx.x * BN;

    float acc[FM][FN][4];
#pragma unroll
    for (int i = 0; i < FM; i++)
#pragma unroll
        for (int j = 0; j < FN; j++)
#pragma unroll
            for (int t = 0; t < 4; t++) acc[i][j][t] = 0.f;

    const int nk = K >> 5;

    // stage-issue lambda (A: BM x 32, B: 32 x BN)
    auto issue = [&](int t, int buf) {
        const int k0 = t << 5;
        float* Ad = As + buf * BM * AST;
        float* Bd = Bs + buf * 32 * BST;
#pragma unroll
        for (int i = 0; i < (BM * 8) / THREADS; i++) {
            const int idx = tid + i * THREADS;
            const int r   = idx >> 3;
            const int k4  = (idx & 7) * 4;
            cp16((uint32_t)__cvta_generic_to_shared(Ad + r * AST + k4),
                 Ap + (size_t)(row0 + r) * lda + k0 + k4);
        }
#pragma unroll
        for (int i = 0; i < (BN * 8) / THREADS; i++) {
            const int idx = tid + i * THREADS;
            const int kr  = idx / (BN / 4);
            const int c4  = (idx % (BN / 4)) * 4;
            cp16((uint32_t)__cvta_generic_to_shared(Bd + kr * BST + c4),
                 Bm + (size_t)(k0 + kr) * N + col0 + c4);
        }
        cp_commit();
    };

    issue(0, 0);
    for (int t = 0; t < nk; t++) {
        if (t + 1 < nk) { issue(t + 1, (t + 1) & 1); cp_wait<1>(); }
        else            { cp_wait<0>(); }
        __syncthreads();

        const float* Ab = As + (t & 1) * BM * AST;
        const float* Bb = Bs + (t & 1) * 32 * BST;
#pragma unroll
        for (int kk = 0; kk < 32; kk += 8) {
            uint32_t af[FM][4];
#pragma unroll
            for (int mf = 0; mf < FM; mf++) {
                const int ar = wm * (BM / WM_) + mf * 16 + gid;
                af[mf][0] = __float_as_uint(Ab[(ar    ) * AST + kk + tid4    ]);
                af[mf][1] = __float_as_uint(Ab[(ar + 8) * AST + kk + tid4    ]);
                af[mf][2] = __float_as_uint(Ab[(ar    ) * AST + kk + tid4 + 4]);
                af[mf][3] = __float_as_uint(Ab[(ar + 8) * AST + kk + tid4 + 4]);
            }
            uint32_t bf[FN][2];
#pragma unroll
            for (int nf = 0; nf < FN; nf++) {
                const int bc = wn * (BN / WN_) + nf * 8 + gid;
                bf[nf][0] = __float_as_uint(Bb[(kk + tid4    ) * BST + bc]);
                bf[nf][1] = __float_as_uint(Bb[(kk + tid4 + 4) * BST + bc]);
            }
#pragma unroll
            for (int mf = 0; mf < FM; mf++)
#pragma unroll
                for (int nf = 0; nf < FN; nf++) {
                    asm volatile(
                        "mma.sync.aligned.m16n8k8.row.col.f32.tf32.tf32.f32 "
                        "{%0,%1,%2,%3}, {%4,%5,%6,%7}, {%8,%9}, {%0,%1,%2,%3};"
                        : "+f"(acc[mf][nf][0]), "+f"(acc[mf][nf][1]),
                          "+f"(acc[mf][nf][2]), "+f"(acc[mf][nf][3])
                        : "r"(af[mf][0]), "r"(af[mf][1]), "r"(af[mf][2]), "r"(af[mf][3]),
                          "r"(bf[nf][0]), "r"(bf[nf][1]));
                }
        }
        __syncthreads();
    }

    // Epilogue
#pragma unroll
    for (int mf = 0; mf < FM; mf++) {
        const int r = row0 + wm * (BM / WM_) + mf * 16 + gid;
#pragma unroll
        for (int nf = 0; nf < FN; nf++) {
            const int c = col0 + wn * (BN / WN_) + nf * 8 + tid4 * 2;
            float v0 = acc[mf][nf][0];
            float v1 = acc[mf][nf][1];
            float v2 = acc[mf][nf][2];
            float v3 = acc[mf][nf][3];
            if (BIASF) {
                v0 += bias[c]; v1 += bias[c + 1]; v2 += bias[c]; v3 += bias[c + 1];
            }
            if (RES) {
                const float2 r0 = *(const float2*)(res + (size_t)r * N + c);
                const float2 r1 = *(const float2*)(res + (size_t)(r + 8) * N + c);
                v0 += r0.x; v1 += r0.y; v2 += r1.x; v3 += r1.y;
            }
            if (RELU) {
                v0 = fmaxf(v0, 0.f); v1 = fmaxf(v1, 0.f);
                v2 = fmaxf(v2, 0.f); v3 = fmaxf(v3, 0.f);
            }
            if (QOUT) {
                v0 = tf32r(v0); v1 = tf32r(v1); v2 = tf32r(v2); v3 = tf32r(v3);
            }
            *(float2*)(Cm + (size_t)r * N + c)       = make_float2(v0, v1);
            *(float2*)(Cm + (size_t)(r + 8) * N + c) = make_float2(v2, v3);
        }
    }
}

// -------------------- FF2 reduce: x += (p0 + p1 + b2) ----------------------------------
__global__ void ff2_reduce_kernel(
    const float* __restrict__ p0, const float* __restrict__ p1,
    const float* __restrict__ b2, float* __restrict__ x)
{
    const int i = blockIdx.x * blockDim.x + threadIdx.x;     // over M_*D_/4
    const int c = i & (D_ / 4 - 1);
    const float4 a = ((const float4*)p0)[i];
    const float4 b = ((const float4*)p1)[i];
    const float4 bb = ((const float4*)b2)[c];
    float4 xx = ((float4*)x)[i];
    xx.x += a.x + b.x + bb.x;
    xx.y += a.y + b.y + bb.y;
    xx.z += a.z + b.z + bb.z;
    xx.w += a.w + b.w + bb.w;
    ((float4*)x)[i] = xx;
}

// -------------------- FFMA GEMM for the K=8 embed only --------------------
__global__ __launch_bounds__(256) void embed_kernel(
    const float* __restrict__ A, const float* __restrict__ Bm,
    const float* __restrict__ bias, float* __restrict__ Cm, int M, int N, int K)
{
    __shared__ float As[8][128];
    __shared__ float Bs[8][128];
    const int tid  = threadIdx.x;
    const int tx   = tid & 15;
    const int ty   = tid >> 4;
    const int row0 = blockIdx.y * 128;
    const int col0 = blockIdx.x * 128;
    const int aRow = tid >> 1;
    const int aCol = (tid & 1) * 4;
    const int bRow = tid >> 5;
    const int bCol = (tid & 31) * 4;

    float acc[8][8];
#pragma unroll
    for (int i = 0; i < 8; i++)
#pragma unroll
        for (int j = 0; j < 8; j++) acc[i][j] = 0.f;

    for (int k0 = 0; k0 < K; k0 += 8) {
        float4 a4 = *(const float4*)(A + (size_t)(row0 + aRow) * K + k0 + aCol);
        As[aCol + 0][aRow] = tf32r(a4.x);
        As[aCol + 1][aRow] = tf32r(a4.y);
        As[aCol + 2][aRow] = tf32r(a4.z);
        As[aCol + 3][aRow] = tf32r(a4.w);
        float4 b4 = *(const float4*)(Bm + (size_t)(k0 + bRow) * N + col0 + bCol);
        Bs[bRow][bCol + 0] = tf32r(b4.x);
        Bs[bRow][bCol + 1] = tf32r(b4.y);
        Bs[bRow][bCol + 2] = tf32r(b4.z);
        Bs[bRow][bCol + 3] = tf32r(b4.w);
        __syncthreads();
#pragma unroll
        for (int kk = 0; kk < 8; kk++) {
            float ra[8], rb[8];
#pragma unroll
            for (int i = 0; i < 8; i++) ra[i] = As[kk][ty * 8 + i];
#pragma unroll
            for (int j = 0; j < 8; j++) rb[j] = Bs[kk][tx * 8 + j];
#pragma unroll
            for (int i = 0; i < 8; i++)
#pragma unroll
                for (int j = 0; j < 8; j++)
                    acc[i][j] += ra[i] * rb[j];
        }
        __syncthreads();
    }
#pragma unroll
    for (int i = 0; i < 8; i++) {
        int r = row0 + ty * 8 + i;
#pragma unroll
        for (int j = 0; j < 8; j++) {
            int c = col0 + tx * 8 + j;
            Cm[(size_t)r * N + c] = acc[i][j] + bias[c];
        }
    }
}

// -------------------- layernorm (warp/row, float4); OUTPUT IS TF32-QUANTIZED -----------
__global__ __launch_bounds__(256) void ln_kernel(
    const float* __restrict__ x, const float* __restrict__ g,
    const float* __restrict__ b, float* __restrict__ out)
{
    const int row  = blockIdx.x * 8 + (threadIdx.x >> 5);
    const int lane = threadIdx.x & 31;
    const float4* xp = (const float4*)(x + (size_t)row * D_);
    const float4 a0 = xp[lane];
    const float4 a1 = xp[lane + 32];

    float s  = a0.x + a0.y + a0.z + a0.w + a1.x + a1.y + a1.z + a1.w;
    float s2 = a0.x*a0.x + a0.y*a0.y + a0.z*a0.z + a0.w*a0.w
             + a1.x*a1.x + a1.y*a1.y + a1.z*a1.z + a1.w*a1.w;
#pragma unroll
    for (int o = 16; o > 0; o >>= 1) {
        s  += __shfl_xor_sync(0xffffffffu, s,  o);
        s2 += __shfl_xor_sync(0xffffffffu, s2, o);
    }
    const float mean = s  * (1.f / 256.f);
    const float var  = s2 * (1.f / 256.f) - mean * mean;
    const float rs   = rsqrtf(var + 1e-5f);

    const float4 g0 = ((const float4*)g)[lane];
    const float4 g1 = ((const float4*)g)[lane + 32];
    const float4 b0 = ((const float4*)b)[lane];
    const float4 b1 = ((const float4*)b)[lane + 32];
    float4* op = (float4*)(out + (size_t)row * D_);
    op[lane]      = make_float4(tf32r((a0.x-mean)*rs*g0.x + b0.x), tf32r((a0.y-mean)*rs*g0.y + b0.y),
                                tf32r((a0.z-mean)*rs*g0.z + b0.z), tf32r((a0.w-mean)*rs*g0.w + b0.w));
    op[lane + 32] = make_float4(tf32r((a1.x-mean)*rs*g1.x + b1.x), tf32r((a1.y-mean)*rs*g1.y + b1.y),
                                tf32r((a1.z-mean)*rs*g1.z + b1.z), tf32r((a1.w-mean)*rs*g1.w + b1.w));
}

// -------------------- RoPE tables (double-precision trig of fp32-rounded angle) --------
__global__ void rope_tables_kernel()
{
    const int t = blockIdx.x * blockDim.x + threadIdx.x;   // C_*16 threads
    const int i = t & 15;
    const int c = t >> 4;
    const float invf = (float)(1.0 / pow(10000.0, (double)i / 16.0));
    const float angf = (float)c * invf;
    g_cos[t] = (float)cos((double)angf);
    g_sin[t] = (float)sin((double)angf);
}

// -------------------- RoPE in-place on q AND k; OUTPUT IS TF32-QUANTIZED ---------------
__global__ void rope_kernel(float* __restrict__ q, float* __restrict__ k)
{
    const int tid = blockIdx.x * blockDim.x + threadIdx.x;  // M_*H_*16 threads
    const int i = tid & 15;
    const int h = (tid >> 4) & 7;
    const int r = tid >> 7;
    const int c = r & (C_ - 1);
    const float cs = g_cos[c * 16 + i];
    const float sn = g_sin[c * 16 + i];
    const size_t off = (size_t)r * D_ + h * DH_;
    {
        float* p = q + off;
        const float t1 = p[i], t2 = p[i + 16];
        p[i]      = tf32r(t1 * cs - t2 * sn);
        p[i + 16] = tf32r(t1 * sn + t2 * cs);
    }
    {
        float* p = k + off;
        const float t1 = p[i], t2 = p[i + 16];
        p[i]      = tf32r(t1 * cs - t2 * sn);
        p[i + 16] = tf32r(t1 * sn + t2 * cs);
    }
}

// -------------------- windowed circular attention --------------------
__global__ __launch_bounds__(128) void attn_kernel(
    const float* __restrict__ q, const float* __restrict__ k,
    const float* __restrict__ v, float* __restrict__ out)
{
    __shared__ float wbuf[4][64];
    const int warp = (blockIdx.x * blockDim.x + threadIdx.x) >> 5;  // (b,h,c)
    const int wib  = (threadIdx.x >> 5);
    const int lane = threadIdx.x & 31;
    const int g    = lane >> 3;
    const int s    = lane & 7;
    const int c = warp & (C_ - 1);
    const int h = (warp >> 11) & (H_ - 1);
    const int b = warp >> 14;
    const int qrow = b * C_ + c;
    const float scale = 0.17677669529663687f;                       // 1/sqrt(32)

    const float4 q4 = ((const float4*)(q + (size_t)qrow * D_ + h * DH_))[s];

    // Phase 1: scores for 4 keys per iteration
#pragma unroll 3
    for (int j0 = 0; j0 < KTOK_; j0 += 4) {
        const int j = j0 + g;
        int kc = c - j; if (kc < 0) kc += C_;
        const float4 k4 = ((const float4*)(k + (size_t)(b * C_ + kc) * D_ + h * DH_))[s];
        float p = q4.x * k4.x + q4.y * k4.y + q4.z * k4.z + q4.w * k4.w;
        p += __shfl_xor_sync(0xffffffffu, p, 1);
        p += __shfl_xor_sync(0xffffffffu, p, 2);
        p += __shfl_xor_sync(0xffffffffu, p, 4);
        if (s == 0) wbuf[wib][j] = p * scale;
    }
    __syncwarp();

    // Phase 2: max + denom (parallel over lanes)
    const float v1 = wbuf[wib][lane];
    const float v2 = (lane < KTOK_ - 32) ? wbuf[wib][lane + 32] : -INFINITY;
    float m = fmaxf(v1, v2);
#pragma unroll
    for (int o = 16; o > 0; o >>= 1) m = fmaxf(m, __shfl_xor_sync(0xffffffffu, m, o));
    const float p1 = __expf(v1 - m);
    const float p2 = (lane < KTOK_ - 32) ? __expf(v2 - m) : 0.f;
    wbuf[wib][lane] = p1;
    if (lane < KTOK_ - 32) wbuf[wib][lane + 32] = p2;
    float d = p1 + p2;
#pragma unroll
    for (int o = 16; o > 0; o >>= 1) d += __shfl_xor_sync(0xffffffffu, d, o);
    const float invd = 1.f / d;
    __syncwarp();

    // Phase 3: output accumulation, 4 keys per iteration
    float4 acc = make_float4(0.f, 0.f, 0.f, 0.f);
#pragma unroll 3
    for (int j0 = 0; j0 < KTOK_; j0 += 4) {
        const int j = j0 + g;
        int kc = c - j; if (kc < 0) kc += C_;
        const float4 v4 = ((const float4*)(v + (size_t)(b * C_ + kc) * D_ + h * DH_))[s];
        const float w = tf32r(wbuf[wib][j] * invd);
        acc.x += w * tf32r(v4.x);
        acc.y += w * tf32r(v4.y);
        acc.z += w * tf32r(v4.z);
        acc.w += w * tf32r(v4.w);
    }
#pragma unroll
    for (int o = 8; o <= 16; o <<= 1) {
        acc.x += __shfl_xor_sync(0xffffffffu, acc.x, o);
        acc.y += __shfl_xor_sync(0xffffffffu, acc.y, o);
        acc.z += __shfl_xor_sync(0xffffffffu, acc.z, o);
        acc.w += __shfl_xor_sync(0xffffffffu, acc.w, o);
    }
    if (g == 0)
        ((float4*)(out + (size_t)qrow * D_ + h * DH_))[s] =
            make_float4(tf32r(acc.x), tf32r(acc.y), tf32r(acc.z), tf32r(acc.w));
}

// -------------------- host orchestration --------------------
extern "C" void kernel_launch(void* const* d_in, const int* in_sizes, int n_in,
                              void* d_out, int out_size)
{
    const float* tok   = (const float*)d_in[0];
    const float* W_in  = (const float*)d_in[1];
    const float* b_in  = (const float*)d_in[2];
    const float* Wq    = (const float*)d_in[3];
    const float* bq    = (const float*)d_in[4];
    const float* Wk    = (const float*)d_in[5];
    const float* bk    = (const float*)d_in[6];
    const float* Wv    = (const float*)d_in[7];
    const float* bv    = (const float*)d_in[8];
    const float* Wo    = (const float*)d_in[9];
    const float* bo    = (const float*)d_in[10];
    const float* ln1g  = (const float*)d_in[11];
    const float* ln1b  = (const float*)d_in[12];
    const float* ln2g  = (const float*)d_in[13];
    const float* ln2b  = (const float*)d_in[14];
    const float* W1    = (const float*)d_in[15];
    const float* b1    = (const float*)d_in[16];
    const float* W2    = (const float*)d_in[17];
    const float* b2    = (const float*)d_in[18];
    const float* W_out = (const float*)d_in[19];
    const float* b_out = (const float*)d_in[20];
    float* out = (float*)d_out;

    float *x, *h, *q, *k, *v, *ao, *ff;
    float *wq, *wk, *wv, *wo, *w1, *w2, *wout;
    cudaGetSymbolAddress((void**)&x,  g_x);
    cudaGetSymbolAddress((void**)&h,  g_h);
    cudaGetSymbolAddress((void**)&q,  g_q);
    cudaGetSymbolAddress((void**)&k,  g_k);
    cudaGetSymbolAddress((void**)&v,  g_v);
    cudaGetSymbolAddress((void**)&ao, g_ao);
    cudaGetSymbolAddress((void**)&ff, g_ff);
    cudaGetSymbolAddress((void**)&wq, g_wq);
    cudaGetSymbolAddress((void**)&wk, g_wk);
    cudaGetSymbolAddress((void**)&wv, g_wv);
    cudaGetSymbolAddress((void**)&wo, g_wo);
    cudaGetSymbolAddress((void**)&w1, g_w1);
    cudaGetSymbolAddress((void**)&w2, g_w2);
    cudaGetSymbolAddress((void**)&wout, g_wout);

    constexpr int SM_BIG   = 2 * 128 * 36 * 4 + 2 * 32 * 136 * 4;   // 71680
    constexpr int SM_SMALL = 2 * 64  * 36 * 4 + 2 * 32 * 72  * 4;   // 36864

    //            BM  BN  WM WN  RELU  RES   QKV3  QOUT  BIASF KSPLIT2
    auto* kQKV = tgemm_kernel<64, 64, 2, 2, false, false, true,  false, true,  false>;
    auto* kRES = tgemm_kernel<64, 64, 2, 2, false, true,  false, false, true,  false>;
    auto* kFF1 = tgemm_kernel<128,128, 2, 2, true,  false, false, true,  true,  false>;
    auto* kFF2 = tgemm_kernel<64, 64, 2, 2, false, false, false, false, false, true >;
    auto* kOUT = tgemm_kernel<128,128, 2, 2, false, false, false, false, true,  false>;
    cudaFuncSetAttribute(kQKV, cudaFuncAttributeMaxDynamicSharedMemorySize, SM_SMALL);
    cudaFuncSetAttribute(kRES, cudaFuncAttributeMaxDynamicSharedMemorySize, SM_SMALL);
    cudaFuncSetAttribute(kFF1, cudaFuncAttributeMaxDynamicSharedMemorySize, SM_BIG);
    cudaFuncSetAttribute(kFF2, cudaFuncAttributeMaxDynamicSharedMemorySize, SM_SMALL);
    cudaFuncSetAttribute(kOUT, cudaFuncAttributeMaxDynamicSharedMemorySize, SM_BIG);

    const dim3 gQKV(D_ / 64, M_ / 64, 3);     // (4, 64, 3)
    const dim3 gRES(D_ / 64, M_ / 64);        // (4, 64)
    const dim3 gFF1(FF_ / 128, M_ / 128);     // (16, 32)
    const dim3 gFF2(D_ / 64, M_ / 64, 2);     // (4, 64, 2) split-K
    const dim3 gO  (NOUT_ / 128, M_ / 128);   // (128, 32)

    // single fused weight prequant (2359296 float4s)
    prequant_kernel<<<(PQ_TOTAL + 255) / 256, 256>>>(Wq, Wk, Wv, Wo, W1, W2, W_out);

    rope_tables_kernel<<<(C_ * 16) / 256, 256>>>();

    // x = tok @ W_in + b_in   (K = 8, FFMA path; x stays fp32)
    embed_kernel<<<dim3(D_ / 128, M_ / 128), 256>>>(tok, W_in, b_in, x, M_, D_, 8);

    for (int l = 0; l < L_; l++) {
        ln_kernel<<<M_ / 8, 256>>>(x, ln1g + l * D_, ln1b + l * D_, h);

        kQKV<<<gQKV, 128, SM_SMALL>>>(h,
            wq + (size_t)l * D_ * D_, bq + l * D_, q, nullptr, D_, D_, D_,
            wk + (size_t)l * D_ * D_, bk + l * D_, k,
            wv + (size_t)l * D_ * D_, bv + l * D_, v);

        rope_kernel<<<(M_ * H_ * 16) / 256, 256>>>(q, k);

        attn_kernel<<<(B_ * H_ * C_ * 32) / 128, 128>>>(q, k, v, ao);

        // x = x + ao @ Wo + bo   (x stays fp32)
        kRES<<<gRES, 128, SM_SMALL>>>(ao,
            wo + (size_t)l * D_ * D_, bo + l * D_, x, x, D_, D_, D_,
            nullptr, nullptr, nullptr, nullptr, nullptr, nullptr);

        ln_kernel<<<M_ / 8, 256>>>(x, ln2g + l * D_, ln2b + l * D_, h);

        // ff = tf32(relu(h @ W1 + b1))
        kFF1<<<gFF1, 128, SM_BIG>>>(h,
            w1 + (size_t)l * D_ * FF_, b1 + l * FF_, ff, nullptr, FF_, D_, D_,
            nullptr, nullptr, nullptr, nullptr, nullptr, nullptr);

        // split-K FF2: p0 = ff[:, :1024] @ W2[:1024, :], p1 = ff[:, 1024:] @ W2[1024:, :]
        // (q/k buffers are free after attention)
        kFF2<<<gFF2, 128, SM_SMALL>>>(ff,
            w2 + (size_t)l * FF_ * D_, nullptr, q, nullptr, D_, FF_ / 2, FF_,
            w2 + (size_t)l * FF_ * D_ + (size_t)(FF_ / 2) * D_, nullptr, k,
            nullptr, nullptr, nullptr);
        // x += p0 + p1 + b2
        ff2_reduce_kernel<<<(M_ * D_ / 4) / 256, 256>>>(q, k, b2 + l * D_, x);
    }

    // xq = tf32(x) ; out = xq @ W_out + b_out   (reuse q buffer as xq)
    qcopy_kernel<<<(M_ * D_ / 4) / 256, 256>>>(x, q, M_ * D_ / 4);
    kOUT<<<gO, 128, SM_BIG>>>(q,
        wout, b_out, out, nullptr, NOUT_, D_, D_,
        nullptr, nullptr, nullptr, nullptr, nullptr, nullptr);
}

// round 10
// speedup vs baseline: 4.9314x; 1.0227x over previous
#include <cuda_runtime.h>
#include <math.h>
#include <stdint.h>

// Problem constants (fixed by setup_inputs)
#define B_      2
#define C_      2048
#define D_      256
#define H_      8
#define L_      4
#define FF_     2048
#define DH_     32
#define NOUT_   16384
#define M_      (B_ * C_)      // 4096
#define KTOK_   60

// -------------------- scratch --------------------
__device__ float g_x [M_ * D_];
__device__ float g_h [M_ * D_];
__device__ float g_q [M_ * D_];
__device__ float g_k [M_ * D_];
__device__ float g_v [M_ * D_];
__device__ float g_ao[M_ * D_];
__device__ float g_ff[M_ * FF_];
__device__ float g_cos[C_ * 16];
__device__ float g_sin[C_ * 16];
// pre-quantized (tf32) weights
__device__ float g_wq[L_ * D_ * D_];
__device__ float g_wk[L_ * D_ * D_];
__device__ float g_wv[L_ * D_ * D_];
__device__ float g_wo[L_ * D_ * D_];
__device__ float g_w1[L_ * D_ * FF_];
__device__ float g_w2[L_ * FF_ * D_];
__device__ float g_wout[D_ * NOUT_];

// TF32 input quantization (round-to-nearest-away), matching cuBLAS/XLA TF32 matmuls.
__device__ __forceinline__ float tf32r(float x) {
    float r;
    asm("cvt.rna.tf32.f32 %0, %1;" : "=f"(r) : "f"(x));
    return r;
}

__device__ __forceinline__ void cp16(uint32_t saddr, const float* gptr) {
    asm volatile("cp.async.cg.shared.global [%0], [%1], 16;" :: "r"(saddr), "l"(gptr));
}
__device__ __forceinline__ void cp_commit() {
    asm volatile("cp.async.commit_group;" ::: "memory");
}
template<int N>
__device__ __forceinline__ void cp_wait() {
    asm volatile("cp.async.wait_group %0;" :: "n"(N) : "memory");
}

// -------------------- single fused weight-prequant kernel (float4 granularity) ---------
#define SEG_A  (L_ * D_ * D_ / 4)        // 65536 per qkv/o weight
#define SEG_W  (L_ * D_ * FF_ / 4)       // 524288 per w1/w2
#define SEG_O  (D_ * NOUT_ / 4)          // 1048576
#define PQ_TOTAL (4 * SEG_A + 2 * SEG_W + SEG_O)   // 2359296

__global__ void prequant_kernel(
    const float* __restrict__ Wq, const float* __restrict__ Wk,
    const float* __restrict__ Wv, const float* __restrict__ Wo,
    const float* __restrict__ W1, const float* __restrict__ W2,
    const float* __restrict__ Wout)
{
    int i = blockIdx.x * blockDim.x + threadIdx.x;
    if (i >= PQ_TOTAL) return;
    const float* src; float* dst;
    if      (i < 1 * SEG_A)             { src = Wq;  dst = g_wq;   i -= 0 * SEG_A; }
    else if (i < 2 * SEG_A)             { src = Wk;  dst = g_wk;   i -= 1 * SEG_A; }
    else if (i < 3 * SEG_A)             { src = Wv;  dst = g_wv;   i -= 2 * SEG_A; }
    else if (i < 4 * SEG_A)             { src = Wo;  dst = g_wo;   i -= 3 * SEG_A; }
    else if (i < 4 * SEG_A + SEG_W)     { src = W1;  dst = g_w1;   i -= 4 * SEG_A; }
    else if (i < 4 * SEG_A + 2 * SEG_W) { src = W2;  dst = g_w2;   i -= 4 * SEG_A + SEG_W; }
    else                                { src = Wout;dst = g_wout; i -= 4 * SEG_A + 2 * SEG_W; }
    float4 a = ((const float4*)src)[i];
    a.x = tf32r(a.x); a.y = tf32r(a.y); a.z = tf32r(a.z); a.w = tf32r(a.w);
    ((float4*)dst)[i] = a;
}

// ==================== TF32 tensor-core GEMM, double-buffered cp.async ====================
// All inputs PRE-QUANTIZED tf32 values. C = A@B [+bias] [+res] [relu] [tf32-out].
// KSPLIT2: blockIdx.z selects K-half. ROPEQK: fuse RoPE+quantize into epilogue for z<2
// (requires BN/WN_==32, FN==4; used by the QKV kernel only).
template<int BM, int BN, int WM_, int WN_, bool RELU, bool RES, bool QKV3, bool QOUT,
         bool BIASF, bool KSPLIT2, bool ROPEQK>
__global__ void tgemm_kernel(
    const float* __restrict__ A,
    const float* __restrict__ B0, const float* __restrict__ bias0, float* __restrict__ C0,
    const float* __restrict__ res,
    int N, int K, int lda,
    const float* B1, const float* bias1, float* C1,
    const float* B2, const float* bias2, float* C2)
{
    constexpr int THREADS = WM_ * WN_ * 32;
    constexpr int AST = 36;         // A smem stride (BK+4)
    constexpr int BST = BN + 8;     // B smem stride
    constexpr int FM  = (BM / WM_) / 16;
    constexpr int FN  = (BN / WN_) / 8;

    extern __shared__ float smem[];
    float* As = smem;                     // [2][BM][AST]
    float* Bs = smem + 2 * BM * AST;      // [2][32][BST]

    const float* Ap = A;
    const float* Bm = B0;  const float* bias = bias0;  float* Cm = C0;
    if (QKV3) {
        if (blockIdx.z == 1)      { Bm = B1; bias = bias1; Cm = C1; }
        else if (blockIdx.z == 2) { Bm = B2; bias = bias2; Cm = C2; }
    }
    if (KSPLIT2) {
        if (blockIdx.z == 1) { Ap = A + K; Bm = B1; Cm = C1; }
    }

    const int tid  = threadIdx.x;
    const int warp = tid >> 5;
    const int lane = tid & 31;
    const int wm   = warp / WN_;
    const int wn   = warp % WN_;
    const int gid  = lane >> 2;
    const int tid4 = lane & 3;

    const int row0 = blockIdx.y * BM;
    const int col0 = blockIdx.x * BN;

    float acc[FM][FN][4];
#pragma unroll
    for (int i = 0; i < FM; i++)
#pragma unroll
        for (int j = 0; j < FN; j++)
#pragma unroll
            for (int t = 0; t < 4; t++) acc[i][j][t] = 0.f;

    const int nk = K >> 5;

    auto issue = [&](int t, int buf) {
        const int k0 = t << 5;
        float* Ad = As + buf * BM * AST;
        float* Bd = Bs + buf * 32 * BST;
#pragma unroll
        for (int i = 0; i < (BM * 8) / THREADS; i++) {
            const int idx = tid + i * THREADS;
            const int r   = idx >> 3;
            const int k4  = (idx & 7) * 4;
            cp16((uint32_t)__cvta_generic_to_shared(Ad + r * AST + k4),
                 Ap + (size_t)(row0 + r) * lda + k0 + k4);
        }
#pragma unroll
        for (int i = 0; i < (BN * 8) / THREADS; i++) {
            const int idx = tid + i * THREADS;
            const int kr  = idx / (BN / 4);
            const int c4  = (idx % (BN / 4)) * 4;
            cp16((uint32_t)__cvta_generic_to_shared(Bd + kr * BST + c4),
                 Bm + (size_t)(k0 + kr) * N + col0 + c4);
        }
        cp_commit();
    };

    issue(0, 0);
    for (int t = 0; t < nk; t++) {
        if (t + 1 < nk) { issue(t + 1, (t + 1) & 1); cp_wait<1>(); }
        else            { cp_wait<0>(); }
        __syncthreads();

        const float* Ab = As + (t & 1) * BM * AST;
        const float* Bb = Bs + (t & 1) * 32 * BST;
#pragma unroll
        for (int kk = 0; kk < 32; kk += 8) {
            uint32_t af[FM][4];
#pragma unroll
            for (int mf = 0; mf < FM; mf++) {
                const int ar = wm * (BM / WM_) + mf * 16 + gid;
                af[mf][0] = __float_as_uint(Ab[(ar    ) * AST + kk + tid4    ]);
                af[mf][1] = __float_as_uint(Ab[(ar + 8) * AST + kk + tid4    ]);
                af[mf][2] = __float_as_uint(Ab[(ar    ) * AST + kk + tid4 + 4]);
                af[mf][3] = __float_as_uint(Ab[(ar + 8) * AST + kk + tid4 + 4]);
            }
            uint32_t bf[FN][2];
#pragma unroll
            for (int nf = 0; nf < FN; nf++) {
                const int bc = wn * (BN / WN_) + nf * 8 + gid;
                bf[nf][0] = __float_as_uint(Bb[(kk + tid4    ) * BST + bc]);
                bf[nf][1] = __float_as_uint(Bb[(kk + tid4 + 4) * BST + bc]);
            }
#pragma unroll
            for (int mf = 0; mf < FM; mf++)
#pragma unroll
                for (int nf = 0; nf < FN; nf++) {
                    asm volatile(
                        "mma.sync.aligned.m16n8k8.row.col.f32.tf32.tf32.f32 "
                        "{%0,%1,%2,%3}, {%4,%5,%6,%7}, {%8,%9}, {%0,%1,%2,%3};"
                        : "+f"(acc[mf][nf][0]), "+f"(acc[mf][nf][1]),
                          "+f"(acc[mf][nf][2]), "+f"(acc[mf][nf][3])
                        : "r"(af[mf][0]), "r"(af[mf][1]), "r"(af[mf][2]), "r"(af[mf][3]),
                          "r"(bf[nf][0]), "r"(bf[nf][1]));
                }
        }
        __syncthreads();
    }

    // ---------------- Epilogue ----------------
    if (ROPEQK) {
        // buffered per-mf epilogue with fused RoPE for q/k slices (blockIdx.z < 2)
        const bool doRope = (blockIdx.z < 2);
#pragma unroll
        for (int mf = 0; mf < FM; mf++) {
            const int r = row0 + wm * (BM / WM_) + mf * 16 + gid;
            float val[FN][4];
#pragma unroll
            for (int nf = 0; nf < FN; nf++) {
                const int c = col0 + wn * (BN / WN_) + nf * 8 + tid4 * 2;
                val[nf][0] = acc[mf][nf][0] + bias[c];
                val[nf][1] = acc[mf][nf][1] + bias[c + 1];
                val[nf][2] = acc[mf][nf][2] + bias[c];
                val[nf][3] = acc[mf][nf][3] + bias[c + 1];
            }
            if (doRope) {
                const int tok1 = r & (C_ - 1);
                const int tok2 = (r + 8) & (C_ - 1);
#pragma unroll
                for (int nf = 0; nf < 2; nf++) {
                    const int i0 = nf * 8 + tid4 * 2;
                    float cs, sn, t1, t2;
                    cs = g_cos[tok1 * 16 + i0];     sn = g_sin[tok1 * 16 + i0];
                    t1 = val[nf][0]; t2 = val[nf + 2][0];
                    val[nf][0]     = t1 * cs - t2 * sn;
                    val[nf + 2][0] = t1 * sn + t2 * cs;
                    cs = g_cos[tok1 * 16 + i0 + 1]; sn = g_sin[tok1 * 16 + i0 + 1];
                    t1 = val[nf][1]; t2 = val[nf + 2][1];
                    val[nf][1]     = t1 * cs - t2 * sn;
                    val[nf + 2][1] = t1 * sn + t2 * cs;
                    cs = g_cos[tok2 * 16 + i0];     sn = g_sin[tok2 * 16 + i0];
                    t1 = val[nf][2]; t2 = val[nf + 2][2];
                    val[nf][2]     = t1 * cs - t2 * sn;
                    val[nf + 2][2] = t1 * sn + t2 * cs;
                    cs = g_cos[tok2 * 16 + i0 + 1]; sn = g_sin[tok2 * 16 + i0 + 1];
                    t1 = val[nf][3]; t2 = val[nf + 2][3];
                    val[nf][3]     = t1 * cs - t2 * sn;
                    val[nf + 2][3] = t1 * sn + t2 * cs;
                }
#pragma unroll
                for (int nf = 0; nf < FN; nf++)
#pragma unroll
                    for (int t = 0; t < 4; t++) val[nf][t] = tf32r(val[nf][t]);
            }
#pragma unroll
            for (int nf = 0; nf < FN; nf++) {
                const int c = col0 + wn * (BN / WN_) + nf * 8 + tid4 * 2;
                *(float2*)(Cm + (size_t)r * N + c)       = make_float2(val[nf][0], val[nf][1]);
                *(float2*)(Cm + (size_t)(r + 8) * N + c) = make_float2(val[nf][2], val[nf][3]);
            }
        }
    } else {
#pragma unroll
        for (int mf = 0; mf < FM; mf++) {
            const int r = row0 + wm * (BM / WM_) + mf * 16 + gid;
#pragma unroll
            for (int nf = 0; nf < FN; nf++) {
                const int c = col0 + wn * (BN / WN_) + nf * 8 + tid4 * 2;
                float v0 = acc[mf][nf][0];
                float v1 = acc[mf][nf][1];
                float v2 = acc[mf][nf][2];
                float v3 = acc[mf][nf][3];
                if (BIASF) {
                    v0 += bias[c]; v1 += bias[c + 1]; v2 += bias[c]; v3 += bias[c + 1];
                }
                if (RES) {
                    const float2 r0 = *(const float2*)(res + (size_t)r * N + c);
                    const float2 r1 = *(const float2*)(res + (size_t)(r + 8) * N + c);
                    v0 += r0.x; v1 += r0.y; v2 += r1.x; v3 += r1.y;
                }
                if (RELU) {
                    v0 = fmaxf(v0, 0.f); v1 = fmaxf(v1, 0.f);
                    v2 = fmaxf(v2, 0.f); v3 = fmaxf(v3, 0.f);
                }
                if (QOUT) {
                    v0 = tf32r(v0); v1 = tf32r(v1); v2 = tf32r(v2); v3 = tf32r(v3);
                }
                *(float2*)(Cm + (size_t)r * N + c)       = make_float2(v0, v1);
                *(float2*)(Cm + (size_t)(r + 8) * N + c) = make_float2(v2, v3);
            }
        }
    }
}

// -------------------- fused FF2-reduce + layernorm (warp/row) --------------------------
// xx = x + p0 + p1 + b2 ; x <- xx ; h <- tf32(LN(xx))
__global__ __launch_bounds__(256) void redln_kernel(
    const float* __restrict__ p0, const float* __restrict__ p1,
    const float* __restrict__ b2, float* __restrict__ x,
    const float* __restrict__ g, const float* __restrict__ b, float* __restrict__ out)
{
    const int row  = blockIdx.x * 8 + (threadIdx.x >> 5);
    const int lane = threadIdx.x & 31;
    const size_t base = (size_t)row * D_;

    float4 a0, a1;
    {
        const float4 xa = ((const float4*)(x + base))[lane];
        const float4 xb = ((const float4*)(x + base))[lane + 32];
        const float4 pa = ((const float4*)(p0 + base))[lane];
        const float4 pb = ((const float4*)(p0 + base))[lane + 32];
        const float4 qa = ((const float4*)(p1 + base))[lane];
        const float4 qb = ((const float4*)(p1 + base))[lane + 32];
        const float4 ba = ((const float4*)b2)[lane];
        const float4 bb = ((const float4*)b2)[lane + 32];
        a0.x = xa.x + (pa.x + qa.x + ba.x);
        a0.y = xa.y + (pa.y + qa.y + ba.y);
        a0.z = xa.z + (pa.z + qa.z + ba.z);
        a0.w = xa.w + (pa.w + qa.w + ba.w);
        a1.x = xb.x + (pb.x + qb.x + bb.x);
        a1.y = xb.y + (pb.y + qb.y + bb.y);
        a1.z = xb.z + (pb.z + qb.z + bb.z);
        a1.w = xb.w + (pb.w + qb.w + bb.w);
        ((float4*)(x + base))[lane]      = a0;
        ((float4*)(x + base))[lane + 32] = a1;
    }

    float s  = a0.x + a0.y + a0.z + a0.w + a1.x + a1.y + a1.z + a1.w;
    float s2 = a0.x*a0.x + a0.y*a0.y + a0.z*a0.z + a0.w*a0.w
             + a1.x*a1.x + a1.y*a1.y + a1.z*a1.z + a1.w*a1.w;
#pragma unroll
    for (int o = 16; o > 0; o >>= 1) {
        s  += __shfl_xor_sync(0xffffffffu, s,  o);
        s2 += __shfl_xor_sync(0xffffffffu, s2, o);
    }
    const float mean = s  * (1.f / 256.f);
    const float var  = s2 * (1.f / 256.f) - mean * mean;
    const float rs   = rsqrtf(var + 1e-5f);

    const float4 g0 = ((const float4*)g)[lane];
    const float4 g1 = ((const float4*)g)[lane + 32];
    const float4 b0 = ((const float4*)b)[lane];
    const float4 b1 = ((const float4*)b)[lane + 32];
    float4* op = (float4*)(out + base);
    op[lane]      = make_float4(tf32r((a0.x-mean)*rs*g0.x + b0.x), tf32r((a0.y-mean)*rs*g0.y + b0.y),
                                tf32r((a0.z-mean)*rs*g0.z + b0.z), tf32r((a0.w-mean)*rs*g0.w + b0.w));
    op[lane + 32] = make_float4(tf32r((a1.x-mean)*rs*g1.x + b1.x), tf32r((a1.y-mean)*rs*g1.y + b1.y),
                                tf32r((a1.z-mean)*rs*g1.z + b1.z), tf32r((a1.w-mean)*rs*g1.w + b1.w));
}

// -------------------- fused final FF2-reduce + tf32 quantize ---------------------------
// xq = tf32(x + p0 + p1 + b2)
__global__ void redq_kernel(
    const float* __restrict__ p0, const float* __restrict__ p1,
    const float* __restrict__ b2, const float* __restrict__ x, float* __restrict__ xq)
{
    const int i = blockIdx.x * blockDim.x + threadIdx.x;     // over M_*D_/4
    const int c = i & (D_ / 4 - 1);
    const float4 a = ((const float4*)p0)[i];
    const float4 b = ((const float4*)p1)[i];
    const float4 bb = ((const float4*)b2)[c];
    const float4 xx = ((const float4*)x)[i];
    float4 o;
    o.x = tf32r(xx.x + (a.x + b.x + bb.x));
    o.y = tf32r(xx.y + (a.y + b.y + bb.y));
    o.z = tf32r(xx.z + (a.z + b.z + bb.z));
    o.w = tf32r(xx.w + (a.w + b.w + bb.w));
    ((float4*)xq)[i] = o;
}

// -------------------- FFMA GEMM for the K=8 embed only --------------------
__global__ __launch_bounds__(256) void embed_kernel(
    const float* __restrict__ A, const float* __restrict__ Bm,
    const float* __restrict__ bias, float* __restrict__ Cm, int M, int N, int K)
{
    __shared__ float As[8][128];
    __shared__ float Bs[8][128];
    const int tid  = threadIdx.x;
    const int tx   = tid & 15;
    const int ty   = tid >> 4;
    const int row0 = blockIdx.y * 128;
    const int col0 = blockIdx.x * 128;
    const int aRow = tid >> 1;
    const int aCol = (tid & 1) * 4;
    const int bRow = tid >> 5;
    const int bCol = (tid & 31) * 4;

    float acc[8][8];
#pragma unroll
    for (int i = 0; i < 8; i++)
#pragma unroll
        for (int j = 0; j < 8; j++) acc[i][j] = 0.f;

    for (int k0 = 0; k0 < K; k0 += 8) {
        float4 a4 = *(const float4*)(A + (size_t)(row0 + aRow) * K + k0 + aCol);
        As[aCol + 0][aRow] = tf32r(a4.x);
        As[aCol + 1][aRow] = tf32r(a4.y);
        As[aCol + 2][aRow] = tf32r(a4.z);
        As[aCol + 3][aRow] = tf32r(a4.w);
        float4 b4 = *(const float4*)(Bm + (size_t)(k0 + bRow) * N + col0 + bCol);
        Bs[bRow][bCol + 0] = tf32r(b4.x);
        Bs[bRow][bCol + 1] = tf32r(b4.y);
        Bs[bRow][bCol + 2] = tf32r(b4.z);
        Bs[bRow][bCol + 3] = tf32r(b4.w);
        __syncthreads();
#pragma unroll
        for (int kk = 0; kk < 8; kk++) {
            float ra[8], rb[8];
#pragma unroll
            for (int i = 0; i < 8; i++) ra[i] = As[kk][ty * 8 + i];
#pragma unroll
            for (int j = 0; j < 8; j++) rb[j] = Bs[kk][tx * 8 + j];
#pragma unroll
            for (int i = 0; i < 8; i++)
#pragma unroll
                for (int j = 0; j < 8; j++)
                    acc[i][j] += ra[i] * rb[j];
        }
        __syncthreads();
    }
#pragma unroll
    for (int i = 0; i < 8; i++) {
        int r = row0 + ty * 8 + i;
#pragma unroll
        for (int j = 0; j < 8; j++) {
            int c = col0 + tx * 8 + j;
            Cm[(size_t)r * N + c] = acc[i][j] + bias[c];
        }
    }
}

// -------------------- layernorm (warp/row, float4); OUTPUT IS TF32-QUANTIZED -----------
__global__ __launch_bounds__(256) void ln_kernel(
    const float* __restrict__ x, const float* __restrict__ g,
    const float* __restrict__ b, float* __restrict__ out)
{
    const int row  = blockIdx.x * 8 + (threadIdx.x >> 5);
    const int lane = threadIdx.x & 31;
    const float4* xp = (const float4*)(x + (size_t)row * D_);
    const float4 a0 = xp[lane];
    const float4 a1 = xp[lane + 32];

    float s  = a0.x + a0.y + a0.z + a0.w + a1.x + a1.y + a1.z + a1.w;
    float s2 = a0.x*a0.x + a0.y*a0.y + a0.z*a0.z + a0.w*a0.w
             + a1.x*a1.x + a1.y*a1.y + a1.z*a1.z + a1.w*a1.w;
#pragma unroll
    for (int o = 16; o > 0; o >>= 1) {
        s  += __shfl_xor_sync(0xffffffffu, s,  o);
        s2 += __shfl_xor_sync(0xffffffffu, s2, o);
    }
    const float mean = s  * (1.f / 256.f);
    const float var  = s2 * (1.f / 256.f) - mean * mean;
    const float rs   = rsqrtf(var + 1e-5f);

    const float4 g0 = ((const float4*)g)[lane];
    const float4 g1 = ((const float4*)g)[lane + 32];
    const float4 b0 = ((const float4*)b)[lane];
    const float4 b1 = ((const float4*)b)[lane + 32];
    float4* op = (float4*)(out + (size_t)row * D_);
    op[lane]      = make_float4(tf32r((a0.x-mean)*rs*g0.x + b0.x), tf32r((a0.y-mean)*rs*g0.y + b0.y),
                                tf32r((a0.z-mean)*rs*g0.z + b0.z), tf32r((a0.w-mean)*rs*g0.w + b0.w));
    op[lane + 32] = make_float4(tf32r((a1.x-mean)*rs*g1.x + b1.x), tf32r((a1.y-mean)*rs*g1.y + b1.y),
                                tf32r((a1.z-mean)*rs*g1.z + b1.z), tf32r((a1.w-mean)*rs*g1.w + b1.w));
}

// -------------------- RoPE tables (double-precision trig of fp32-rounded angle) --------
__global__ void rope_tables_kernel()
{
    const int t = blockIdx.x * blockDim.x + threadIdx.x;   // C_*16 threads
    const int i = t & 15;
    const int c = t >> 4;
    const float invf = (float)(1.0 / pow(10000.0, (double)i / 16.0));
    const float angf = (float)c * invf;
    g_cos[t] = (float)cos((double)angf);
    g_sin[t] = (float)sin((double)angf);
}

// -------------------- windowed circular attention --------------------
__global__ __launch_bounds__(128) void attn_kernel(
    const float* __restrict__ q, const float* __restrict__ k,
    const float* __restrict__ v, float* __restrict__ out)
{
    __shared__ float wbuf[4][64];
    const int warp = (blockIdx.x * blockDim.x + threadIdx.x) >> 5;  // (b,h,c)
    const int wib  = (threadIdx.x >> 5);
    const int lane = threadIdx.x & 31;
    const int g    = lane >> 3;
    const int s    = lane & 7;
    const int c = warp & (C_ - 1);
    const int h = (warp >> 11) & (H_ - 1);
    const int b = warp >> 14;
    const int qrow = b * C_ + c;
    const float scale = 0.17677669529663687f;                       // 1/sqrt(32)

    const float4 q4 = ((const float4*)(q + (size_t)qrow * D_ + h * DH_))[s];

    // Phase 1: scores for 4 keys per iteration
#pragma unroll 3
    for (int j0 = 0; j0 < KTOK_; j0 += 4) {
        const int j = j0 + g;
        int kc = c - j; if (kc < 0) kc += C_;
        const float4 k4 = ((const float4*)(k + (size_t)(b * C_ + kc) * D_ + h * DH_))[s];
        float p = q4.x * k4.x + q4.y * k4.y + q4.z * k4.z + q4.w * k4.w;
        p += __shfl_xor_sync(0xffffffffu, p, 1);
        p += __shfl_xor_sync(0xffffffffu, p, 2);
        p += __shfl_xor_sync(0xffffffffu, p, 4);
        if (s == 0) wbuf[wib][j] = p * scale;
    }
    __syncwarp();

    // Phase 2: max + denom (parallel over lanes)
    const float v1 = wbuf[wib][lane];
    const float v2 = (lane < KTOK_ - 32) ? wbuf[wib][lane + 32] : -INFINITY;
    float m = fmaxf(v1, v2);
#pragma unroll
    for (int o = 16; o > 0; o >>= 1) m = fmaxf(m, __shfl_xor_sync(0xffffffffu, m, o));
    const float p1 = __expf(v1 - m);
    const float p2 = (lane < KTOK_ - 32) ? __expf(v2 - m) : 0.f;
    wbuf[wib][lane] = p1;
    if (lane < KTOK_ - 32) wbuf[wib][lane + 32] = p2;
    float d = p1 + p2;
#pragma unroll
    for (int o = 16; o > 0; o >>= 1) d += __shfl_xor_sync(0xffffffffu, d, o);
    const float invd = 1.f / d;
    __syncwarp();

    // Phase 3: output accumulation, 4 keys per iteration
    float4 acc = make_float4(0.f, 0.f, 0.f, 0.f);
#pragma unroll 3
    for (int j0 = 0; j0 < KTOK_; j0 += 4) {
        const int j = j0 + g;
        int kc = c - j; if (kc < 0) kc += C_;
        const float4 v4 = ((const float4*)(v + (size_t)(b * C_ + kc) * D_ + h * DH_))[s];
        const float w = tf32r(wbuf[wib][j] * invd);
        acc.x += w * tf32r(v4.x);
        acc.y += w * tf32r(v4.y);
        acc.z += w * tf32r(v4.z);
        acc.w += w * tf32r(v4.w);
    }
#pragma unroll
    for (int o = 8; o <= 16; o <<= 1) {
        acc.x += __shfl_xor_sync(0xffffffffu, acc.x, o);
        acc.y += __shfl_xor_sync(0xffffffffu, acc.y, o);
        acc.z += __shfl_xor_sync(0xffffffffu, acc.z, o);
        acc.w += __shfl_xor_sync(0xffffffffu, acc.w, o);
    }
    if (g == 0)
        ((float4*)(out + (size_t)qrow * D_ + h * DH_))[s] =
            make_float4(tf32r(acc.x), tf32r(acc.y), tf32r(acc.z), tf32r(acc.w));
}

// -------------------- host orchestration --------------------
extern "C" void kernel_launch(void* const* d_in, const int* in_sizes, int n_in,
                              void* d_out, int out_size)
{
    const float* tok   = (const float*)d_in[0];
    const float* W_in  = (const float*)d_in[1];
    const float* b_in  = (const float*)d_in[2];
    const float* Wq    = (const float*)d_in[3];
    const float* bq    = (const float*)d_in[4];
    const float* Wk    = (const float*)d_in[5];
    const float* bk    = (const float*)d_in[6];
    const float* Wv    = (const float*)d_in[7];
    const float* bv    = (const float*)d_in[8];
    const float* Wo    = (const float*)d_in[9];
    const float* bo    = (const float*)d_in[10];
    const float* ln1g  = (const float*)d_in[11];
    const float* ln1b  = (const float*)d_in[12];
    const float* ln2g  = (const float*)d_in[13];
    const float* ln2b  = (const float*)d_in[14];
    const float* W1    = (const float*)d_in[15];
    const float* b1    = (const float*)d_in[16];
    const float* W2    = (const float*)d_in[17];
    const float* b2    = (const float*)d_in[18];
    const float* W_out = (const float*)d_in[19];
    const float* b_out = (const float*)d_in[20];
    float* out = (float*)d_out;

    float *x, *h, *q, *k, *v, *ao, *ff;
    float *wq, *wk, *wv, *wo, *w1, *w2, *wout;
    cudaGetSymbolAddress((void**)&x,  g_x);
    cudaGetSymbolAddress((void**)&h,  g_h);
    cudaGetSymbolAddress((void**)&q,  g_q);
    cudaGetSymbolAddress((void**)&k,  g_k);
    cudaGetSymbolAddress((void**)&v,  g_v);
    cudaGetSymbolAddress((void**)&ao, g_ao);
    cudaGetSymbolAddress((void**)&ff, g_ff);
    cudaGetSymbolAddress((void**)&wq, g_wq);
    cudaGetSymbolAddress((void**)&wk, g_wk);
    cudaGetSymbolAddress((void**)&wv, g_wv);
    cudaGetSymbolAddress((void**)&wo, g_wo);
    cudaGetSymbolAddress((void**)&w1, g_w1);
    cudaGetSymbolAddress((void**)&w2, g_w2);
    cudaGetSymbolAddress((void**)&wout, g_wout);

    constexpr int SM_BIG   = 2 * 128 * 36 * 4 + 2 * 32 * 136 * 4;   // 71680
    constexpr int SM_SMALL = 2 * 64  * 36 * 4 + 2 * 32 * 72  * 4;   // 36864

    //            BM  BN  WM WN  RELU  RES   QKV3  QOUT  BIASF KSPLIT2 ROPEQK
    auto* kQKV = tgemm_kernel<64, 64, 2, 2, false, false, true,  false, true,  false, true >;
    auto* kRES = tgemm_kernel<64, 64, 2, 2, false, true,  false, false, true,  false, false>;
    auto* kFF1 = tgemm_kernel<128,128, 2, 2, true,  false, false, true,  true,  false, false>;
    auto* kFF2 = tgemm_kernel<64, 64, 2, 2, false, false, false, false, false, true,  false>;
    auto* kOUT = tgemm_kernel<128,128, 2, 2, false, false, false, false, true,  false, false>;
    cudaFuncSetAttribute(kQKV, cudaFuncAttributeMaxDynamicSharedMemorySize, SM_SMALL);
    cudaFuncSetAttribute(kRES, cudaFuncAttributeMaxDynamicSharedMemorySize, SM_SMALL);
    cudaFuncSetAttribute(kFF1, cudaFuncAttributeMaxDynamicSharedMemorySize, SM_BIG);
    cudaFuncSetAttribute(kFF2, cudaFuncAttributeMaxDynamicSharedMemorySize, SM_SMALL);
    cudaFuncSetAttribute(kOUT, cudaFuncAttributeMaxDynamicSharedMemorySize, SM_BIG);

    const dim3 gQKV(D_ / 64, M_ / 64, 3);     // (4, 64, 3)
    const dim3 gRES(D_ / 64, M_ / 64);        // (4, 64)
    const dim3 gFF1(FF_ / 128, M_ / 128);     // (16, 32)
    const dim3 gFF2(D_ / 64, M_ / 64, 2);     // (4, 64, 2) split-K
    const dim3 gO  (NOUT_ / 128, M_ / 128);   // (128, 32)

    prequant_kernel<<<(PQ_TOTAL + 255) / 256, 256>>>(Wq, Wk, Wv, Wo, W1, W2, W_out);
    rope_tables_kernel<<<(C_ * 16) / 256, 256>>>();

    // x = tok @ W_in + b_in   (K = 8, FFMA path; x stays fp32)
    embed_kernel<<<dim3(D_ / 128, M_ / 128), 256>>>(tok, W_in, b_in, x, M_, D_, 8);

    // layer-0 ln1 (later layers get it fused with the FF2 reduce)
    ln_kernel<<<M_ / 8, 256>>>(x, ln1g, ln1b, h);

    for (int l = 0; l < L_; l++) {
        // q/k outputs get RoPE + tf32-quantize fused in the epilogue; v raw fp32
        kQKV<<<gQKV, 128, SM_SMALL>>>(h,
            wq + (size_t)l * D_ * D_, bq + l * D_, q, nullptr, D_, D_, D_,
            wk + (size_t)l * D_ * D_, bk + l * D_, k,
            wv + (size_t)l * D_ * D_, bv + l * D_, v);

        attn_kernel<<<(B_ * H_ * C_ * 32) / 128, 128>>>(q, k, v, ao);

        // x = x + ao @ Wo + bo
        kRES<<<gRES, 128, SM_SMALL>>>(ao,
            wo + (size_t)l * D_ * D_, bo + l * D_, x, x, D_, D_, D_,
            nullptr, nullptr, nullptr, nullptr, nullptr, nullptr);

        ln_kernel<<<M_ / 8, 256>>>(x, ln2g + l * D_, ln2b + l * D_, h);

        // ff = tf32(relu(h @ W1 + b1))
        kFF1<<<gFF1, 128, SM_BIG>>>(h,
            w1 + (size_t)l * D_ * FF_, b1 + l * FF_, ff, nullptr, FF_, D_, D_,
            nullptr, nullptr, nullptr, nullptr, nullptr, nullptr);

        // split-K FF2 partials into q/k (free after attention)
        kFF2<<<gFF2, 128, SM_SMALL>>>(ff,
            w2 + (size_t)l * FF_ * D_, nullptr, q, nullptr, D_, FF_ / 2, FF_,
            w2 + (size_t)l * FF_ * D_ + (size_t)(FF_ / 2) * D_, nullptr, k,
            nullptr, nullptr, nullptr);

        if (l + 1 < L_) {
            // x += p0+p1+b2, then ln1 of next layer, fused
            redln_kernel<<<M_ / 8, 256>>>(q, k, b2 + l * D_, x,
                                          ln1g + (l + 1) * D_, ln1b + (l + 1) * D_, h);
        } else {
            // final: xq = tf32(x + p0+p1+b2)  (into v, free)
            redq_kernel<<<(M_ * D_ / 4) / 256, 256>>>(q, k, b2 + l * D_, x, v);
        }
    }

    // out = xq @ W_out + b_out
    kOUT<<<gO, 128, SM_BIG>>>(v,
        wout, b_out, out, nullptr, NOUT_, D_, D_,
        nullptr, nullptr, nullptr, nullptr, nullptr, nullptr);
}